// round 8
// baseline (speedup 1.0000x reference)
#include <cuda_runtime.h>
#include <cuda_bf16.h>
#include <stdint.h>
#include <math.h>

#define N_TOK 4096
#define D_DIM 1024
#define H_DIM 4096
#define O_DIM 1024
#define E_NUM 8

// ---------------- static device scratch (~400 MB total) ----------------
__device__ __nv_bfloat16 g_xhi[(size_t)N_TOK * D_DIM];
__device__ __nv_bfloat16 g_xlo[(size_t)N_TOK * D_DIM];
__device__ __nv_bfloat16 g_w1hi[(size_t)E_NUM * H_DIM * D_DIM];   // [e][h][d] (transposed)
__device__ __nv_bfloat16 g_w1lo[(size_t)E_NUM * H_DIM * D_DIM];
__device__ __nv_bfloat16 g_w2hi[(size_t)E_NUM * O_DIM * H_DIM];   // [e][o][h] (transposed)
__device__ __nv_bfloat16 g_w2lo[(size_t)E_NUM * O_DIM * H_DIM];
__device__ __nv_bfloat16 g_hhi[(size_t)2 * N_TOK * H_DIM];        // compact slots
__device__ __nv_bfloat16 g_hlo[(size_t)2 * N_TOK * H_DIM];
__device__ int   g_sel[N_TOK * 2];
__device__ float g_w[N_TOK * 2];
__device__ int   g_list[E_NUM * N_TOK];
__device__ float g_lw[E_NUM * N_TOK];
__device__ int   g_count[E_NUM];

// ---------------- PTX helpers (sm_80-baseline only) ----------------
__device__ __forceinline__ uint32_t smem_u32(const void* p) {
    uint32_t a;
    asm("{ .reg .u64 t; cvta.to.shared.u64 t, %1; cvt.u32.u64 %0, t; }" : "=r"(a) : "l"(p));
    return a;
}

#define CPASYNC16(dst, src) \
    asm volatile("cp.async.cg.shared.global [%0], [%1], 16;" :: "r"(dst), "l"(src))
#define CP_COMMIT() asm volatile("cp.async.commit_group;" ::: "memory")
#define CP_WAIT2()  asm volatile("cp.async.wait_group 2;" ::: "memory")

#define LDSM4(r, a) \
    asm volatile("ldmatrix.sync.aligned.m8n8.x4.shared.b16 {%0,%1,%2,%3}, [%4];" \
                 : "=r"((r)[0]), "=r"((r)[1]), "=r"((r)[2]), "=r"((r)[3]) : "r"(a))

#define MMA16816(c, a, b0, b1) \
    asm volatile("mma.sync.aligned.m16n8k16.row.col.f32.bf16.bf16.f32 " \
                 "{%0,%1,%2,%3}, {%4,%5,%6,%7}, {%8,%9}, {%0,%1,%2,%3};" \
                 : "+f"((c)[0]), "+f"((c)[1]), "+f"((c)[2]), "+f"((c)[3]) \
                 : "r"((a)[0]), "r"((a)[1]), "r"((a)[2]), "r"((a)[3]), "r"(b0), "r"(b1))

// ---------------- smem layout ----------------
// toks[128] | wls[128] | bias[128] | 3 stages x { Ahi | Alo | Bhi | Blo }
// tile = 128 rows x 80 bytes (32 bf16 + 8 pad) = 10240 B; stage = 40960 B
#define SM_TOKS 0
#define SM_WLS  512
#define SM_BIAS 1024
#define SM_BUF  2048
#define TILE_B   10240
#define STAGE_B  40960
#define NSTAGE   3
#define SMEM_BYTES (SM_BUF + NSTAGE * STAGE_B)

// ---------------- gate + x split (fused) ----------------
__global__ void gate_kernel(const float* __restrict__ x, const float* __restrict__ Wg) {
    int t = blockIdx.x;
    int tid = threadIdx.x;  // 256 threads, 4 cols each
    float4 v = ((const float4*)(x + (size_t)t * D_DIM))[tid];
    float vv[4] = {v.x, v.y, v.z, v.w};

    uint32_t ph[2], pl[2];
#pragma unroll
    for (int j = 0; j < 4; j++) {
        __nv_bfloat16 hb = __float2bfloat16(vv[j]);
        __nv_bfloat16 lb = __float2bfloat16(vv[j] - __bfloat162float(hb));
        uint32_t hbits = (uint32_t)__bfloat16_as_ushort(hb);
        uint32_t lbits = (uint32_t)__bfloat16_as_ushort(lb);
        if (j & 1) { ph[j >> 1] |= hbits << 16; pl[j >> 1] |= lbits << 16; }
        else       { ph[j >> 1]  = hbits;       pl[j >> 1]  = lbits; }
    }
    size_t xo = ((size_t)t * D_DIM + tid * 4) >> 2;
    ((uint2*)g_xhi)[xo] = make_uint2(ph[0], ph[1]);
    ((uint2*)g_xlo)[xo] = make_uint2(pl[0], pl[1]);

    float acc[E_NUM];
#pragma unroll
    for (int e = 0; e < E_NUM; e++) acc[e] = 0.f;
#pragma unroll
    for (int j = 0; j < 4; j++) {
        int d = tid * 4 + j;
        const float4 w0 = *(const float4*)(Wg + (size_t)d * E_NUM);
        const float4 w1 = *(const float4*)(Wg + (size_t)d * E_NUM + 4);
        acc[0] += vv[j] * w0.x; acc[1] += vv[j] * w0.y;
        acc[2] += vv[j] * w0.z; acc[3] += vv[j] * w0.w;
        acc[4] += vv[j] * w1.x; acc[5] += vv[j] * w1.y;
        acc[6] += vv[j] * w1.z; acc[7] += vv[j] * w1.w;
    }

    __shared__ float red[E_NUM][256];
#pragma unroll
    for (int e = 0; e < E_NUM; e++) red[e][tid] = acc[e];
    __syncthreads();
    for (int s = 128; s > 0; s >>= 1) {
        if (tid < s) {
#pragma unroll
            for (int e = 0; e < E_NUM; e++) red[e][tid] += red[e][tid + s];
        }
        __syncthreads();
    }
    if (tid == 0) {
        float v2[E_NUM];
#pragma unroll
        for (int e = 0; e < E_NUM; e++) v2[e] = fmaxf(red[e][0], 0.f);
        int i1 = 0; float m1 = v2[0];
#pragma unroll
        for (int e = 1; e < E_NUM; e++) if (v2[e] > m1) { m1 = v2[e]; i1 = e; }
        int i2 = -1; float m2 = -1e30f;
#pragma unroll
        for (int e = 0; e < E_NUM; e++) if (e != i1 && v2[e] > m2) { m2 = v2[e]; i2 = e; }
        float eb = __expf(m2 - m1);
        float inv = 1.f / (1.f + eb);
        g_sel[t * 2 + 0] = i1;  g_w[t * 2 + 0] = inv;
        g_sel[t * 2 + 1] = i2;  g_w[t * 2 + 1] = eb * inv;
    }
}

// ---------------- per-expert token lists (deterministic scan) ----------------
__global__ void build_lists_kernel() {
    int e = blockIdx.x;
    int tid = threadIdx.x;  // 1024
    __shared__ int ssum[1024];
    int t0 = tid * 4;
    int flag[4]; float wv[4];
    int cnt = 0;
#pragma unroll
    for (int j = 0; j < 4; j++) {
        int t = t0 + j;
        int s0 = g_sel[t * 2], s1 = g_sel[t * 2 + 1];
        flag[j] = 0; wv[j] = 0.f;
        if (s0 == e)      { flag[j] = 1; wv[j] = g_w[t * 2]; }
        else if (s1 == e) { flag[j] = 1; wv[j] = g_w[t * 2 + 1]; }
        cnt += flag[j];
    }
    ssum[tid] = cnt;
    __syncthreads();
    for (int off = 1; off < 1024; off <<= 1) {
        int v = (tid >= off) ? ssum[tid - off] : 0;
        __syncthreads();
        ssum[tid] += v;
        __syncthreads();
    }
    int pos = ssum[tid] - cnt;
#pragma unroll
    for (int j = 0; j < 4; j++) {
        if (flag[j]) {
            g_list[e * N_TOK + pos] = t0 + j;
            g_lw[e * N_TOK + pos] = wv[j];
            pos++;
        }
    }
    if (tid == 1023) g_count[e] = ssum[1023];
}

// ---------------- conversions ----------------
__device__ __forceinline__ void split_bf16(float v, __nv_bfloat16& h, __nv_bfloat16& l) {
    h = __float2bfloat16(v);
    l = __float2bfloat16(v - __bfloat162float(h));
}

__device__ __forceinline__ int slot_base(int e) {
    int b = 0;
#pragma unroll
    for (int i = 0; i < E_NUM; i++) if (i < e) b += g_count[i];
    return b;
}

// in: [e][R][C] fp32 -> out hi/lo: [e][C][R] bf16, packed uint2 stores
__global__ void transpose_split_kernel(const float* __restrict__ in, int which, int R, int C) {
    int e = blockIdx.z;
    const float* src = in + (size_t)e * R * C;
    __nv_bfloat16* ohi = (which ? g_w2hi : g_w1hi) + (size_t)e * R * C;
    __nv_bfloat16* olo = (which ? g_w2lo : g_w1lo) + (size_t)e * R * C;
    __shared__ float t[32][33];
    int tid = threadIdx.x;
    int tx = tid & 31, ty = tid >> 5;
    int c0 = blockIdx.x * 32, r0 = blockIdx.y * 32;
#pragma unroll
    for (int j = 0; j < 4; j++)
        t[ty + 8 * j][tx] = src[(size_t)(r0 + ty + 8 * j) * C + c0 + tx];
    __syncthreads();
    int cc = tid >> 3, g = tid & 7;
    float v0 = t[g * 4 + 0][cc], v1 = t[g * 4 + 1][cc];
    float v2 = t[g * 4 + 2][cc], v3 = t[g * 4 + 3][cc];
    __nv_bfloat16 h0, l0, h1, l1, h2, l2, h3, l3;
    split_bf16(v0, h0, l0); split_bf16(v1, h1, l1);
    split_bf16(v2, h2, l2); split_bf16(v3, h3, l3);
    uint2 uh = make_uint2(
        (uint32_t)__bfloat16_as_ushort(h0) | ((uint32_t)__bfloat16_as_ushort(h1) << 16),
        (uint32_t)__bfloat16_as_ushort(h2) | ((uint32_t)__bfloat16_as_ushort(h3) << 16));
    uint2 ul = make_uint2(
        (uint32_t)__bfloat16_as_ushort(l0) | ((uint32_t)__bfloat16_as_ushort(l1) << 16),
        (uint32_t)__bfloat16_as_ushort(l2) | ((uint32_t)__bfloat16_as_ushort(l3) << 16));
    size_t ob = (size_t)(c0 + cc) * R + r0 + g * 4;
    *(uint2*)(ohi + ob) = uh;
    *(uint2*)(olo + ob) = ul;
}

// =============================================================================
// GEMM1: h[slot] = relu(x[tok] @ W1t[e]^T + b1[e])   (hi/lo bf16 out)
// CTA tile 128x128, BK=32, 8 warps, warp tile 32x64, 3-stage cp.async pipeline
// =============================================================================
__global__ void __launch_bounds__(256) ffn1_kernel(const float* __restrict__ b1) {
    int e = blockIdx.z;
    int cnt = g_count[e];
    int rowTile = blockIdx.y * 128;
    if (rowTile >= cnt) return;
    int sbase = slot_base(e);
    int colTile = blockIdx.x * 128;

    extern __shared__ char sm[];
    uint32_t sb = smem_u32(sm);
    int tid = threadIdx.x;
    int*   toksS = (int*)(sm + SM_TOKS);
    float* biasS = (float*)(sm + SM_BIAS);

    if (tid < 128) {
        int r = rowTile + tid;
        toksS[tid] = (r < cnt) ? g_list[e * N_TOK + r] : 0;
        biasS[tid] = b1[(size_t)e * H_DIM + colTile + tid];
    }
    __syncthreads();

    const int NIT = D_DIM / 32;  // 32

    auto load_stage = [&](int p, int it) {
        int k0 = it * 32;
        uint32_t base = sb + SM_BUF + p * STAGE_B;
#pragma unroll
        for (int j = 0; j < 8; j++) {
            int idx = j * 256 + tid;
            int tile = idx >> 9, v = idx & 511, row = v >> 2, ch = v & 3;
            uint32_t dst = base + tile * TILE_B + row * 80 + ch * 16;
            const __nv_bfloat16* src;
            if (tile == 0)      src = g_xhi + (size_t)toksS[row] * D_DIM + k0 + ch * 8;
            else if (tile == 1) src = g_xlo + (size_t)toksS[row] * D_DIM + k0 + ch * 8;
            else if (tile == 2) src = g_w1hi + (size_t)(e * H_DIM + colTile + row) * D_DIM + k0 + ch * 8;
            else                src = g_w1lo + (size_t)(e * H_DIM + colTile + row) * D_DIM + k0 + ch * 8;
            CPASYNC16(dst, src);
        }
    };

    int lane = tid & 31, w = tid >> 5;
    int wm = w & 3, wn = w >> 2;
    uint32_t aOff[2];
#pragma unroll
    for (int mi = 0; mi < 2; mi++)
        aOff[mi] = (uint32_t)(wm * 32 + mi * 16 + (lane & 15)) * 80 + (lane >> 4) * 16;
    uint32_t bOff[4];
#pragma unroll
    for (int np = 0; np < 4; np++) {
        int n = wn * 64 + np * 16 + (lane & 7) + ((lane >= 16) ? 8 : 0);
        bOff[np] = (uint32_t)n * 80 + ((lane & 8) ? 16 : 0);
    }

    float c[64];
#pragma unroll
    for (int i = 0; i < 64; i++) c[i] = 0.f;

    load_stage(0, 0); CP_COMMIT();
    load_stage(1, 1); CP_COMMIT();
    load_stage(2, 2); CP_COMMIT();

    int p = 0;
    for (int it = 0; it < NIT; it++) {
        CP_WAIT2();
        __syncthreads();
        uint32_t base = sb + SM_BUF + p * STAGE_B;
#pragma unroll
        for (int ks = 0; ks < 2; ks++) {
            uint32_t ah[8], al[8], bh[16], bl[16];
            LDSM4(ah + 0, base + aOff[0] + ks * 32);
            LDSM4(ah + 4, base + aOff[1] + ks * 32);
            LDSM4(al + 0, base + TILE_B + aOff[0] + ks * 32);
            LDSM4(al + 4, base + TILE_B + aOff[1] + ks * 32);
#pragma unroll
            for (int np = 0; np < 4; np++) {
                LDSM4(bh + np * 4, base + 2 * TILE_B + bOff[np] + ks * 32);
                LDSM4(bl + np * 4, base + 3 * TILE_B + bOff[np] + ks * 32);
            }
#pragma unroll
            for (int mi = 0; mi < 2; mi++)
#pragma unroll
                for (int nb = 0; nb < 8; nb++) {
                    float* cc = c + (mi * 8 + nb) * 4;
                    int bi = (nb >> 1) * 4 + (nb & 1) * 2;
                    MMA16816(cc, ah + mi * 4, bh[bi], bh[bi + 1]);
                    MMA16816(cc, ah + mi * 4, bl[bi], bl[bi + 1]);
                    MMA16816(cc, al + mi * 4, bh[bi], bh[bi + 1]);
                }
        }
        __syncthreads();
        if (it + NSTAGE < NIT) load_stage(p, it + NSTAGE);
        CP_COMMIT();
        p = (p == NSTAGE - 1) ? 0 : p + 1;
    }

    int g = lane >> 2, tq = lane & 3;
#pragma unroll
    for (int mi = 0; mi < 2; mi++)
#pragma unroll
        for (int half = 0; half < 2; half++) {
            int rloc = wm * 32 + mi * 16 + half * 8 + g;
            if (rowTile + rloc >= cnt) continue;
            size_t hb = ((size_t)(sbase + rowTile + rloc)) * H_DIM + colTile;
#pragma unroll
            for (int nb = 0; nb < 8; nb++) {
                int col = wn * 64 + nb * 8 + tq * 2;
                float v0 = fmaxf(c[(mi * 8 + nb) * 4 + half * 2 + 0] + biasS[col], 0.f);
                float v1 = fmaxf(c[(mi * 8 + nb) * 4 + half * 2 + 1] + biasS[col + 1], 0.f);
                __nv_bfloat16 h0, l0, h1, l1;
                split_bf16(v0, h0, l0); split_bf16(v1, h1, l1);
                *(uint32_t*)(g_hhi + hb + col) =
                    (uint32_t)__bfloat16_as_ushort(h0) | ((uint32_t)__bfloat16_as_ushort(h1) << 16);
                *(uint32_t*)(g_hlo + hb + col) =
                    (uint32_t)__bfloat16_as_ushort(l0) | ((uint32_t)__bfloat16_as_ushort(l1) << 16);
            }
        }
}

// =============================================================================
// GEMM2: out[tok] += w * relu(h[slot] @ W2t[e]^T + b2[e])   (3-stage pipeline)
// =============================================================================
__global__ void __launch_bounds__(256) ffn2_kernel(const float* __restrict__ b2,
                                                   float* __restrict__ out) {
    int e = blockIdx.z;
    int cnt = g_count[e];
    int rowTile = blockIdx.y * 128;
    if (rowTile >= cnt) return;
    int sbase = slot_base(e);
    int colTile = blockIdx.x * 128;

    extern __shared__ char sm[];
    uint32_t sb = smem_u32(sm);
    int tid = threadIdx.x;
    int*   toksS = (int*)(sm + SM_TOKS);
    float* wlsS  = (float*)(sm + SM_WLS);
    float* biasS = (float*)(sm + SM_BIAS);

    if (tid < 128) {
        int r = rowTile + tid;
        bool v = (r < cnt);
        toksS[tid] = v ? g_list[e * N_TOK + r] : 0;
        wlsS[tid]  = v ? g_lw[e * N_TOK + r] : 0.f;
        biasS[tid] = b2[(size_t)e * O_DIM + colTile + tid];
    }
    __syncthreads();

    const int NIT = H_DIM / 32;  // 128

    auto load_stage = [&](int p, int it) {
        int k0 = it * 32;
        uint32_t base = sb + SM_BUF + p * STAGE_B;
#pragma unroll
        for (int j = 0; j < 8; j++) {
            int idx = j * 256 + tid;
            int tile = idx >> 9, v = idx & 511, row = v >> 2, ch = v & 3;
            uint32_t dst = base + tile * TILE_B + row * 80 + ch * 16;
            const __nv_bfloat16* src;
            int arow = sbase + rowTile + row;
            if (arow >= sbase + cnt) arow = sbase;   // clamp (weight 0 in epilogue)
            if (tile == 0)      src = g_hhi + (size_t)arow * H_DIM + k0 + ch * 8;
            else if (tile == 1) src = g_hlo + (size_t)arow * H_DIM + k0 + ch * 8;
            else if (tile == 2) src = g_w2hi + (size_t)(e * O_DIM + colTile + row) * H_DIM + k0 + ch * 8;
            else                src = g_w2lo + (size_t)(e * O_DIM + colTile + row) * H_DIM + k0 + ch * 8;
            CPASYNC16(dst, src);
        }
    };

    int lane = tid & 31, w = tid >> 5;
    int wm = w & 3, wn = w >> 2;
    uint32_t aOff[2];
#pragma unroll
    for (int mi = 0; mi < 2; mi++)
        aOff[mi] = (uint32_t)(wm * 32 + mi * 16 + (lane & 15)) * 80 + (lane >> 4) * 16;
    uint32_t bOff[4];
#pragma unroll
    for (int np = 0; np < 4; np++) {
        int n = wn * 64 + np * 16 + (lane & 7) + ((lane >= 16) ? 8 : 0);
        bOff[np] = (uint32_t)n * 80 + ((lane & 8) ? 16 : 0);
    }

    float c[64];
#pragma unroll
    for (int i = 0; i < 64; i++) c[i] = 0.f;

    load_stage(0, 0); CP_COMMIT();
    load_stage(1, 1); CP_COMMIT();
    load_stage(2, 2); CP_COMMIT();

    int p = 0;
    for (int it = 0; it < NIT; it++) {
        CP_WAIT2();
        __syncthreads();
        uint32_t base = sb + SM_BUF + p * STAGE_B;
#pragma unroll
        for (int ks = 0; ks < 2; ks++) {
            uint32_t ah[8], al[8], bh[16], bl[16];
            LDSM4(ah + 0, base + aOff[0] + ks * 32);
            LDSM4(ah + 4, base + aOff[1] + ks * 32);
            LDSM4(al + 0, base + TILE_B + aOff[0] + ks * 32);
            LDSM4(al + 4, base + TILE_B + aOff[1] + ks * 32);
#pragma unroll
            for (int np = 0; np < 4; np++) {
                LDSM4(bh + np * 4, base + 2 * TILE_B + bOff[np] + ks * 32);
                LDSM4(bl + np * 4, base + 3 * TILE_B + bOff[np] + ks * 32);
            }
#pragma unroll
            for (int mi = 0; mi < 2; mi++)
#pragma unroll
                for (int nb = 0; nb < 8; nb++) {
                    float* cc = c + (mi * 8 + nb) * 4;
                    int bi = (nb >> 1) * 4 + (nb & 1) * 2;
                    MMA16816(cc, ah + mi * 4, bh[bi], bh[bi + 1]);
                    MMA16816(cc, ah + mi * 4, bl[bi], bl[bi + 1]);
                    MMA16816(cc, al + mi * 4, bh[bi], bh[bi + 1]);
                }
        }
        __syncthreads();
        if (it + NSTAGE < NIT) load_stage(p, it + NSTAGE);
        CP_COMMIT();
        p = (p == NSTAGE - 1) ? 0 : p + 1;
    }

    int g = lane >> 2, tq = lane & 3;
#pragma unroll
    for (int mi = 0; mi < 2; mi++)
#pragma unroll
        for (int half = 0; half < 2; half++) {
            int rloc = wm * 32 + mi * 16 + half * 8 + g;
            if (rowTile + rloc >= cnt) continue;
            int tok = toksS[rloc];
            float wc = wlsS[rloc];
            float* orow = out + (size_t)tok * O_DIM + colTile;
#pragma unroll
            for (int nb = 0; nb < 8; nb++) {
                int col = wn * 64 + nb * 8 + tq * 2;
                float v0 = fmaxf(c[(mi * 8 + nb) * 4 + half * 2 + 0] + biasS[col], 0.f) * wc;
                float v1 = fmaxf(c[(mi * 8 + nb) * 4 + half * 2 + 1] + biasS[col + 1], 0.f) * wc;
                atomicAdd(orow + col, v0);
                atomicAdd(orow + col + 1, v1);
            }
        }
}

// ---------------- host ----------------
extern "C" void kernel_launch(void* const* d_in, const int* in_sizes, int n_in,
                              void* d_out, int out_size) {
    const float* x  = (const float*)d_in[0];
    const float* Wg = (const float*)d_in[1];
    const float* W1 = (const float*)d_in[2];
    const float* b1 = (const float*)d_in[3];
    const float* W2 = (const float*)d_in[4];
    const float* b2 = (const float*)d_in[5];
    float* out = (float*)d_out;

    cudaFuncSetAttribute(ffn1_kernel, cudaFuncAttributeMaxDynamicSharedMemorySize, SMEM_BYTES);
    cudaFuncSetAttribute(ffn2_kernel, cudaFuncAttributeMaxDynamicSharedMemorySize, SMEM_BYTES);

    // ncu captures the 4th kernel launch -> put ffn1 there.
    transpose_split_kernel<<<dim3(H_DIM / 32, D_DIM / 32, E_NUM), 256>>>(W1, 0, D_DIM, H_DIM);
    gate_kernel<<<N_TOK, 256>>>(x, Wg);
    build_lists_kernel<<<E_NUM, 1024>>>();
    ffn1_kernel<<<dim3(H_DIM / 128, N_TOK / 128, E_NUM), 256, SMEM_BYTES>>>(b1);
    transpose_split_kernel<<<dim3(O_DIM / 32, H_DIM / 32, E_NUM), 256>>>(W2, 1, H_DIM, O_DIM);
    cudaMemsetAsync(out, 0, (size_t)N_TOK * O_DIM * sizeof(float), 0);
    ffn2_kernel<<<dim3(O_DIM / 128, N_TOK / 128, E_NUM), 256, SMEM_BYTES>>>(b2, out);
}

// round 9
// speedup vs baseline: 1.1778x; 1.1778x over previous
#include <cuda_runtime.h>
#include <cuda_bf16.h>
#include <stdint.h>
#include <math.h>

#define N_TOK 4096
#define D_DIM 1024
#define H_DIM 4096
#define O_DIM 1024
#define E_NUM 8

// ---------------- static device scratch (~400 MB total) ----------------
__device__ __nv_bfloat16 g_xhi[(size_t)N_TOK * D_DIM];
__device__ __nv_bfloat16 g_xlo[(size_t)N_TOK * D_DIM];
__device__ __nv_bfloat16 g_w1hi[(size_t)E_NUM * H_DIM * D_DIM];   // [e][h][d] (transposed)
__device__ __nv_bfloat16 g_w1lo[(size_t)E_NUM * H_DIM * D_DIM];
__device__ __nv_bfloat16 g_w2hi[(size_t)E_NUM * O_DIM * H_DIM];   // [e][o][h] (transposed)
__device__ __nv_bfloat16 g_w2lo[(size_t)E_NUM * O_DIM * H_DIM];
__device__ __nv_bfloat16 g_hhi[(size_t)2 * N_TOK * H_DIM];        // compact slots
__device__ __nv_bfloat16 g_hlo[(size_t)2 * N_TOK * H_DIM];
__device__ int   g_sel[N_TOK * 2];
__device__ float g_w[N_TOK * 2];
__device__ int   g_list[E_NUM * N_TOK];
__device__ float g_lw[E_NUM * N_TOK];
__device__ int   g_count[E_NUM];

// ---------------- PTX helpers (sm_80-baseline only) ----------------
__device__ __forceinline__ uint32_t smem_u32(const void* p) {
    uint32_t a;
    asm("{ .reg .u64 t; cvta.to.shared.u64 t, %1; cvt.u32.u64 %0, t; }" : "=r"(a) : "l"(p));
    return a;
}

#define CPASYNC16(dst, src) \
    asm volatile("cp.async.cg.shared.global [%0], [%1], 16;" :: "r"(dst), "l"(src))
#define CP_COMMIT() asm volatile("cp.async.commit_group;" ::: "memory")
#define CP_WAIT1()  asm volatile("cp.async.wait_group 1;" ::: "memory")

#define LDSM4(r, a) \
    asm volatile("ldmatrix.sync.aligned.m8n8.x4.shared.b16 {%0,%1,%2,%3}, [%4];" \
                 : "=r"((r)[0]), "=r"((r)[1]), "=r"((r)[2]), "=r"((r)[3]) : "r"(a))

#define MMA16816(c, a, b0, b1) \
    asm volatile("mma.sync.aligned.m16n8k16.row.col.f32.bf16.bf16.f32 " \
                 "{%0,%1,%2,%3}, {%4,%5,%6,%7}, {%8,%9}, {%0,%1,%2,%3};" \
                 : "+f"((c)[0]), "+f"((c)[1]), "+f"((c)[2]), "+f"((c)[3]) \
                 : "r"((a)[0]), "r"((a)[1]), "r"((a)[2]), "r"((a)[3]), "r"(b0), "r"(b1))

// ---------------- smem layout ----------------
// toks[128] | wls[128] | bias[128] | 2 stages x { Ahi | Alo | Bhi | Blo }
// tile = 128 rows x 80 bytes (32 bf16 + 8 pad) = 10240 B; stage = 40960 B
// SMEM_BYTES = 83968 -> 2 CTAs/SM fit in 168 KB (228 KB carveout)
#define SM_TOKS 0
#define SM_WLS  512
#define SM_BIAS 1024
#define SM_BUF  2048
#define TILE_B   10240
#define STAGE_B  40960
#define SMEM_BYTES (SM_BUF + 2 * STAGE_B)

// ---------------- gate + x split (fused) ----------------
__global__ void gate_kernel(const float* __restrict__ x, const float* __restrict__ Wg) {
    int t = blockIdx.x;
    int tid = threadIdx.x;  // 256 threads, 4 cols each
    float4 v = ((const float4*)(x + (size_t)t * D_DIM))[tid];
    float vv[4] = {v.x, v.y, v.z, v.w};

    uint32_t ph[2], pl[2];
#pragma unroll
    for (int j = 0; j < 4; j++) {
        __nv_bfloat16 hb = __float2bfloat16(vv[j]);
        __nv_bfloat16 lb = __float2bfloat16(vv[j] - __bfloat162float(hb));
        uint32_t hbits = (uint32_t)__bfloat16_as_ushort(hb);
        uint32_t lbits = (uint32_t)__bfloat16_as_ushort(lb);
        if (j & 1) { ph[j >> 1] |= hbits << 16; pl[j >> 1] |= lbits << 16; }
        else       { ph[j >> 1]  = hbits;       pl[j >> 1]  = lbits; }
    }
    size_t xo = ((size_t)t * D_DIM + tid * 4) >> 2;
    ((uint2*)g_xhi)[xo] = make_uint2(ph[0], ph[1]);
    ((uint2*)g_xlo)[xo] = make_uint2(pl[0], pl[1]);

    float acc[E_NUM];
#pragma unroll
    for (int e = 0; e < E_NUM; e++) acc[e] = 0.f;
#pragma unroll
    for (int j = 0; j < 4; j++) {
        int d = tid * 4 + j;
        const float4 w0 = *(const float4*)(Wg + (size_t)d * E_NUM);
        const float4 w1 = *(const float4*)(Wg + (size_t)d * E_NUM + 4);
        acc[0] += vv[j] * w0.x; acc[1] += vv[j] * w0.y;
        acc[2] += vv[j] * w0.z; acc[3] += vv[j] * w0.w;
        acc[4] += vv[j] * w1.x; acc[5] += vv[j] * w1.y;
        acc[6] += vv[j] * w1.z; acc[7] += vv[j] * w1.w;
    }

    __shared__ float red[E_NUM][256];
#pragma unroll
    for (int e = 0; e < E_NUM; e++) red[e][tid] = acc[e];
    __syncthreads();
    for (int s = 128; s > 0; s >>= 1) {
        if (tid < s) {
#pragma unroll
            for (int e = 0; e < E_NUM; e++) red[e][tid] += red[e][tid + s];
        }
        __syncthreads();
    }
    if (tid == 0) {
        float v2[E_NUM];
#pragma unroll
        for (int e = 0; e < E_NUM; e++) v2[e] = fmaxf(red[e][0], 0.f);
        int i1 = 0; float m1 = v2[0];
#pragma unroll
        for (int e = 1; e < E_NUM; e++) if (v2[e] > m1) { m1 = v2[e]; i1 = e; }
        int i2 = -1; float m2 = -1e30f;
#pragma unroll
        for (int e = 0; e < E_NUM; e++) if (e != i1 && v2[e] > m2) { m2 = v2[e]; i2 = e; }
        float eb = __expf(m2 - m1);
        float inv = 1.f / (1.f + eb);
        g_sel[t * 2 + 0] = i1;  g_w[t * 2 + 0] = inv;
        g_sel[t * 2 + 1] = i2;  g_w[t * 2 + 1] = eb * inv;
    }
}

// ---------------- per-expert token lists (deterministic scan) ----------------
__global__ void build_lists_kernel() {
    int e = blockIdx.x;
    int tid = threadIdx.x;  // 1024
    __shared__ int ssum[1024];
    int t0 = tid * 4;
    int flag[4]; float wv[4];
    int cnt = 0;
#pragma unroll
    for (int j = 0; j < 4; j++) {
        int t = t0 + j;
        int s0 = g_sel[t * 2], s1 = g_sel[t * 2 + 1];
        flag[j] = 0; wv[j] = 0.f;
        if (s0 == e)      { flag[j] = 1; wv[j] = g_w[t * 2]; }
        else if (s1 == e) { flag[j] = 1; wv[j] = g_w[t * 2 + 1]; }
        cnt += flag[j];
    }
    ssum[tid] = cnt;
    __syncthreads();
    for (int off = 1; off < 1024; off <<= 1) {
        int v = (tid >= off) ? ssum[tid - off] : 0;
        __syncthreads();
        ssum[tid] += v;
        __syncthreads();
    }
    int pos = ssum[tid] - cnt;
#pragma unroll
    for (int j = 0; j < 4; j++) {
        if (flag[j]) {
            g_list[e * N_TOK + pos] = t0 + j;
            g_lw[e * N_TOK + pos] = wv[j];
            pos++;
        }
    }
    if (tid == 1023) g_count[e] = ssum[1023];
}

// ---------------- conversions ----------------
__device__ __forceinline__ void split_bf16(float v, __nv_bfloat16& h, __nv_bfloat16& l) {
    h = __float2bfloat16(v);
    l = __float2bfloat16(v - __bfloat162float(h));
}

__device__ __forceinline__ int slot_base(int e) {
    int b = 0;
#pragma unroll
    for (int i = 0; i < E_NUM; i++) if (i < e) b += g_count[i];
    return b;
}

// in: [e][R][C] fp32 -> out hi/lo: [e][C][R] bf16, packed uint2 stores
__global__ void transpose_split_kernel(const float* __restrict__ in, int which, int R, int C) {
    int e = blockIdx.z;
    const float* src = in + (size_t)e * R * C;
    __nv_bfloat16* ohi = (which ? g_w2hi : g_w1hi) + (size_t)e * R * C;
    __nv_bfloat16* olo = (which ? g_w2lo : g_w1lo) + (size_t)e * R * C;
    __shared__ float t[32][33];
    int tid = threadIdx.x;
    int tx = tid & 31, ty = tid >> 5;
    int c0 = blockIdx.x * 32, r0 = blockIdx.y * 32;
#pragma unroll
    for (int j = 0; j < 4; j++)
        t[ty + 8 * j][tx] = src[(size_t)(r0 + ty + 8 * j) * C + c0 + tx];
    __syncthreads();
    int cc = tid >> 3, g = tid & 7;
    float v0 = t[g * 4 + 0][cc], v1 = t[g * 4 + 1][cc];
    float v2 = t[g * 4 + 2][cc], v3 = t[g * 4 + 3][cc];
    __nv_bfloat16 h0, l0, h1, l1, h2, l2, h3, l3;
    split_bf16(v0, h0, l0); split_bf16(v1, h1, l1);
    split_bf16(v2, h2, l2); split_bf16(v3, h3, l3);
    uint2 uh = make_uint2(
        (uint32_t)__bfloat16_as_ushort(h0) | ((uint32_t)__bfloat16_as_ushort(h1) << 16),
        (uint32_t)__bfloat16_as_ushort(h2) | ((uint32_t)__bfloat16_as_ushort(h3) << 16));
    uint2 ul = make_uint2(
        (uint32_t)__bfloat16_as_ushort(l0) | ((uint32_t)__bfloat16_as_ushort(l1) << 16),
        (uint32_t)__bfloat16_as_ushort(l2) | ((uint32_t)__bfloat16_as_ushort(l3) << 16));
    size_t ob = (size_t)(c0 + cc) * R + r0 + g * 4;
    *(uint2*)(ohi + ob) = uh;
    *(uint2*)(olo + ob) = ul;
}

// =============================================================================
// GEMM1: h[slot] = relu(x[tok] @ W1t[e]^T + b1[e])   (hi/lo bf16 out)
// CTA tile 128x128, BK=32, 8 warps, warp tile 32x64, 2-stage cp.async pipeline
// __launch_bounds__(256, 2): 2 CTAs/SM (16 warps) for latency hiding
// =============================================================================
__global__ void __launch_bounds__(256, 2) ffn1_kernel(const float* __restrict__ b1) {
    int e = blockIdx.z;
    int cnt = g_count[e];
    int rowTile = blockIdx.y * 128;
    if (rowTile >= cnt) return;
    int sbase = slot_base(e);
    int colTile = blockIdx.x * 128;

    extern __shared__ char sm[];
    uint32_t sb = smem_u32(sm);
    int tid = threadIdx.x;
    int*   toksS = (int*)(sm + SM_TOKS);
    float* biasS = (float*)(sm + SM_BIAS);

    if (tid < 128) {
        int r = rowTile + tid;
        toksS[tid] = (r < cnt) ? g_list[e * N_TOK + r] : 0;
        biasS[tid] = b1[(size_t)e * H_DIM + colTile + tid];
    }
    __syncthreads();

    const int NIT = D_DIM / 32;  // 32

    auto load_stage = [&](int p, int it) {
        int k0 = it * 32;
        uint32_t base = sb + SM_BUF + p * STAGE_B;
#pragma unroll
        for (int j = 0; j < 8; j++) {
            int idx = j * 256 + tid;
            int tile = idx >> 9, v = idx & 511, row = v >> 2, ch = v & 3;
            uint32_t dst = base + tile * TILE_B + row * 80 + ch * 16;
            const __nv_bfloat16* src;
            if (tile == 0)      src = g_xhi + (size_t)toksS[row] * D_DIM + k0 + ch * 8;
            else if (tile == 1) src = g_xlo + (size_t)toksS[row] * D_DIM + k0 + ch * 8;
            else if (tile == 2) src = g_w1hi + (size_t)(e * H_DIM + colTile + row) * D_DIM + k0 + ch * 8;
            else                src = g_w1lo + (size_t)(e * H_DIM + colTile + row) * D_DIM + k0 + ch * 8;
            CPASYNC16(dst, src);
        }
    };

    int lane = tid & 31, w = tid >> 5;
    int wm = w & 3, wn = w >> 2;
    uint32_t aOff[2];
#pragma unroll
    for (int mi = 0; mi < 2; mi++)
        aOff[mi] = (uint32_t)(wm * 32 + mi * 16 + (lane & 15)) * 80 + (lane >> 4) * 16;
    uint32_t bOff[4];
#pragma unroll
    for (int np = 0; np < 4; np++) {
        int n = wn * 64 + np * 16 + (lane & 7) + ((lane >= 16) ? 8 : 0);
        bOff[np] = (uint32_t)n * 80 + ((lane & 8) ? 16 : 0);
    }

    float c[64];
#pragma unroll
    for (int i = 0; i < 64; i++) c[i] = 0.f;

    load_stage(0, 0); CP_COMMIT();
    load_stage(1, 1); CP_COMMIT();

    for (int it = 0; it < NIT; it++) {
        int p = it & 1;
        CP_WAIT1();
        __syncthreads();
        uint32_t base = sb + SM_BUF + p * STAGE_B;
#pragma unroll
        for (int ks = 0; ks < 2; ks++) {
            uint32_t ah[8], al[8], bh[16], bl[16];
            LDSM4(ah + 0, base + aOff[0] + ks * 32);
            LDSM4(ah + 4, base + aOff[1] + ks * 32);
            LDSM4(al + 0, base + TILE_B + aOff[0] + ks * 32);
            LDSM4(al + 4, base + TILE_B + aOff[1] + ks * 32);
#pragma unroll
            for (int np = 0; np < 4; np++) {
                LDSM4(bh + np * 4, base + 2 * TILE_B + bOff[np] + ks * 32);
                LDSM4(bl + np * 4, base + 3 * TILE_B + bOff[np] + ks * 32);
            }
#pragma unroll
            for (int mi = 0; mi < 2; mi++)
#pragma unroll
                for (int nb = 0; nb < 8; nb++) {
                    float* cc = c + (mi * 8 + nb) * 4;
                    int bi = (nb >> 1) * 4 + (nb & 1) * 2;
                    MMA16816(cc, ah + mi * 4, bh[bi], bh[bi + 1]);
                    MMA16816(cc, ah + mi * 4, bl[bi], bl[bi + 1]);
                    MMA16816(cc, al + mi * 4, bh[bi], bh[bi + 1]);
                }
        }
        __syncthreads();
        if (it + 2 < NIT) load_stage(p, it + 2);
        CP_COMMIT();
    }

    int g = lane >> 2, tq = lane & 3;
#pragma unroll
    for (int mi = 0; mi < 2; mi++)
#pragma unroll
        for (int half = 0; half < 2; half++) {
            int rloc = wm * 32 + mi * 16 + half * 8 + g;
            if (rowTile + rloc >= cnt) continue;
            size_t hb = ((size_t)(sbase + rowTile + rloc)) * H_DIM + colTile;
#pragma unroll
            for (int nb = 0; nb < 8; nb++) {
                int col = wn * 64 + nb * 8 + tq * 2;
                float v0 = fmaxf(c[(mi * 8 + nb) * 4 + half * 2 + 0] + biasS[col], 0.f);
                float v1 = fmaxf(c[(mi * 8 + nb) * 4 + half * 2 + 1] + biasS[col + 1], 0.f);
                __nv_bfloat16 h0, l0, h1, l1;
                split_bf16(v0, h0, l0); split_bf16(v1, h1, l1);
                *(uint32_t*)(g_hhi + hb + col) =
                    (uint32_t)__bfloat16_as_ushort(h0) | ((uint32_t)__bfloat16_as_ushort(h1) << 16);
                *(uint32_t*)(g_hlo + hb + col) =
                    (uint32_t)__bfloat16_as_ushort(l0) | ((uint32_t)__bfloat16_as_ushort(l1) << 16);
            }
        }
}

// =============================================================================
// GEMM2: out[tok] += w * relu(h[slot] @ W2t[e]^T + b2[e])   (2-stage, 2 CTA/SM)
// =============================================================================
__global__ void __launch_bounds__(256, 2) ffn2_kernel(const float* __restrict__ b2,
                                                      float* __restrict__ out) {
    int e = blockIdx.z;
    int cnt = g_count[e];
    int rowTile = blockIdx.y * 128;
    if (rowTile >= cnt) return;
    int sbase = slot_base(e);
    int colTile = blockIdx.x * 128;

    extern __shared__ char sm[];
    uint32_t sb = smem_u32(sm);
    int tid = threadIdx.x;
    int*   toksS = (int*)(sm + SM_TOKS);
    float* wlsS  = (float*)(sm + SM_WLS);
    float* biasS = (float*)(sm + SM_BIAS);

    if (tid < 128) {
        int r = rowTile + tid;
        bool v = (r < cnt);
        toksS[tid] = v ? g_list[e * N_TOK + r] : 0;
        wlsS[tid]  = v ? g_lw[e * N_TOK + r] : 0.f;
        biasS[tid] = b2[(size_t)e * O_DIM + colTile + tid];
    }
    __syncthreads();

    const int NIT = H_DIM / 32;  // 128

    auto load_stage = [&](int p, int it) {
        int k0 = it * 32;
        uint32_t base = sb + SM_BUF + p * STAGE_B;
#pragma unroll
        for (int j = 0; j < 8; j++) {
            int idx = j * 256 + tid;
            int tile = idx >> 9, v = idx & 511, row = v >> 2, ch = v & 3;
            uint32_t dst = base + tile * TILE_B + row * 80 + ch * 16;
            const __nv_bfloat16* src;
            int arow = sbase + rowTile + row;
            if (arow >= sbase + cnt) arow = sbase;   // clamp (weight 0 in epilogue)
            if (tile == 0)      src = g_hhi + (size_t)arow * H_DIM + k0 + ch * 8;
            else if (tile == 1) src = g_hlo + (size_t)arow * H_DIM + k0 + ch * 8;
            else if (tile == 2) src = g_w2hi + (size_t)(e * O_DIM + colTile + row) * H_DIM + k0 + ch * 8;
            else                src = g_w2lo + (size_t)(e * O_DIM + colTile + row) * H_DIM + k0 + ch * 8;
            CPASYNC16(dst, src);
        }
    };

    int lane = tid & 31, w = tid >> 5;
    int wm = w & 3, wn = w >> 2;
    uint32_t aOff[2];
#pragma unroll
    for (int mi = 0; mi < 2; mi++)
        aOff[mi] = (uint32_t)(wm * 32 + mi * 16 + (lane & 15)) * 80 + (lane >> 4) * 16;
    uint32_t bOff[4];
#pragma unroll
    for (int np = 0; np < 4; np++) {
        int n = wn * 64 + np * 16 + (lane & 7) + ((lane >= 16) ? 8 : 0);
        bOff[np] = (uint32_t)n * 80 + ((lane & 8) ? 16 : 0);
    }

    float c[64];
#pragma unroll
    for (int i = 0; i < 64; i++) c[i] = 0.f;

    load_stage(0, 0); CP_COMMIT();
    load_stage(1, 1); CP_COMMIT();

    for (int it = 0; it < NIT; it++) {
        int p = it & 1;
        CP_WAIT1();
        __syncthreads();
        uint32_t base = sb + SM_BUF + p * STAGE_B;
#pragma unroll
        for (int ks = 0; ks < 2; ks++) {
            uint32_t ah[8], al[8], bh[16], bl[16];
            LDSM4(ah + 0, base + aOff[0] + ks * 32);
            LDSM4(ah + 4, base + aOff[1] + ks * 32);
            LDSM4(al + 0, base + TILE_B + aOff[0] + ks * 32);
            LDSM4(al + 4, base + TILE_B + aOff[1] + ks * 32);
#pragma unroll
            for (int np = 0; np < 4; np++) {
                LDSM4(bh + np * 4, base + 2 * TILE_B + bOff[np] + ks * 32);
                LDSM4(bl + np * 4, base + 3 * TILE_B + bOff[np] + ks * 32);
            }
#pragma unroll
            for (int mi = 0; mi < 2; mi++)
#pragma unroll
                for (int nb = 0; nb < 8; nb++) {
                    float* cc = c + (mi * 8 + nb) * 4;
                    int bi = (nb >> 1) * 4 + (nb & 1) * 2;
                    MMA16816(cc, ah + mi * 4, bh[bi], bh[bi + 1]);
                    MMA16816(cc, ah + mi * 4, bl[bi], bl[bi + 1]);
                    MMA16816(cc, al + mi * 4, bh[bi], bh[bi + 1]);
                }
        }
        __syncthreads();
        if (it + 2 < NIT) load_stage(p, it + 2);
        CP_COMMIT();
    }

    int g = lane >> 2, tq = lane & 3;
#pragma unroll
    for (int mi = 0; mi < 2; mi++)
#pragma unroll
        for (int half = 0; half < 2; half++) {
            int rloc = wm * 32 + mi * 16 + half * 8 + g;
            if (rowTile + rloc >= cnt) continue;
            int tok = toksS[rloc];
            float wc = wlsS[rloc];
            float* orow = out + (size_t)tok * O_DIM + colTile;
#pragma unroll
            for (int nb = 0; nb < 8; nb++) {
                int col = wn * 64 + nb * 8 + tq * 2;
                float v0 = fmaxf(c[(mi * 8 + nb) * 4 + half * 2 + 0] + biasS[col], 0.f) * wc;
                float v1 = fmaxf(c[(mi * 8 + nb) * 4 + half * 2 + 1] + biasS[col + 1], 0.f) * wc;
                atomicAdd(orow + col, v0);
                atomicAdd(orow + col + 1, v1);
            }
        }
}

// ---------------- host ----------------
extern "C" void kernel_launch(void* const* d_in, const int* in_sizes, int n_in,
                              void* d_out, int out_size) {
    const float* x  = (const float*)d_in[0];
    const float* Wg = (const float*)d_in[1];
    const float* W1 = (const float*)d_in[2];
    const float* b1 = (const float*)d_in[3];
    const float* W2 = (const float*)d_in[4];
    const float* b2 = (const float*)d_in[5];
    float* out = (float*)d_out;

    cudaFuncSetAttribute(ffn1_kernel, cudaFuncAttributeMaxDynamicSharedMemorySize, SMEM_BYTES);
    cudaFuncSetAttribute(ffn2_kernel, cudaFuncAttributeMaxDynamicSharedMemorySize, SMEM_BYTES);

    // ncu captures the 4th kernel launch -> ffn1.
    transpose_split_kernel<<<dim3(H_DIM / 32, D_DIM / 32, E_NUM), 256>>>(W1, 0, D_DIM, H_DIM);
    gate_kernel<<<N_TOK, 256>>>(x, Wg);
    build_lists_kernel<<<E_NUM, 1024>>>();
    ffn1_kernel<<<dim3(H_DIM / 128, N_TOK / 128, E_NUM), 256, SMEM_BYTES>>>(b1);
    transpose_split_kernel<<<dim3(O_DIM / 32, H_DIM / 32, E_NUM), 256>>>(W2, 1, H_DIM, O_DIM);
    cudaMemsetAsync(out, 0, (size_t)N_TOK * O_DIM * sizeof(float), 0);
    ffn2_kernel<<<dim3(O_DIM / 128, N_TOK / 128, E_NUM), 256, SMEM_BYTES>>>(b2, out);
}

// round 10
// speedup vs baseline: 1.3916x; 1.1815x over previous
#include <cuda_runtime.h>
#include <cuda_bf16.h>
#include <stdint.h>
#include <math.h>

#define N_TOK 4096
#define D_DIM 1024
#define H_DIM 4096
#define O_DIM 1024
#define E_NUM 8

// ---------------- static device scratch (~400 MB total) ----------------
__device__ __nv_bfloat16 g_xhi[(size_t)N_TOK * D_DIM];
__device__ __nv_bfloat16 g_xlo[(size_t)N_TOK * D_DIM];
__device__ __nv_bfloat16 g_w1hi[(size_t)E_NUM * H_DIM * D_DIM];   // [e][h][d] (transposed)
__device__ __nv_bfloat16 g_w1lo[(size_t)E_NUM * H_DIM * D_DIM];
__device__ __nv_bfloat16 g_w2hi[(size_t)E_NUM * O_DIM * H_DIM];   // [e][o][h] (transposed)
__device__ __nv_bfloat16 g_w2lo[(size_t)E_NUM * O_DIM * H_DIM];
__device__ __nv_bfloat16 g_hhi[(size_t)2 * N_TOK * H_DIM];        // compact slots
__device__ __nv_bfloat16 g_hlo[(size_t)2 * N_TOK * H_DIM];
__device__ int   g_sel[N_TOK * 2];
__device__ float g_w[N_TOK * 2];
__device__ int   g_list[E_NUM * N_TOK];
__device__ float g_lw[E_NUM * N_TOK];
__device__ int   g_count[E_NUM];

// ---------------- PTX helpers (sm_80-baseline only) ----------------
__device__ __forceinline__ uint32_t smem_u32(const void* p) {
    uint32_t a;
    asm("{ .reg .u64 t; cvta.to.shared.u64 t, %1; cvt.u32.u64 %0, t; }" : "=r"(a) : "l"(p));
    return a;
}

#define CPASYNC16(dst, src) \
    asm volatile("cp.async.cg.shared.global [%0], [%1], 16;" :: "r"(dst), "l"(src))
#define CP_COMMIT() asm volatile("cp.async.commit_group;" ::: "memory")
#define CP_WAIT1()  asm volatile("cp.async.wait_group 1;" ::: "memory")

#define LDSM4(r, a) \
    asm volatile("ldmatrix.sync.aligned.m8n8.x4.shared.b16 {%0,%1,%2,%3}, [%4];" \
                 : "=r"((r)[0]), "=r"((r)[1]), "=r"((r)[2]), "=r"((r)[3]) : "r"(a))

#define MMA16816(c, a, b0, b1) \
    asm volatile("mma.sync.aligned.m16n8k16.row.col.f32.bf16.bf16.f32 " \
                 "{%0,%1,%2,%3}, {%4,%5,%6,%7}, {%8,%9}, {%0,%1,%2,%3};" \
                 : "+f"((c)[0]), "+f"((c)[1]), "+f"((c)[2]), "+f"((c)[3]) \
                 : "r"((a)[0]), "r"((a)[1]), "r"((a)[2]), "r"((a)[3]), "r"(b0), "r"(b1))

// ---------------- smem layout ----------------
// Swizzled tiles: 128 rows x 64 B, chunk c at byte ((c ^ ((row>>1)&3)) * 16).
// Conflict-free for ldmatrix 8-row phases and cp.async writes.
// tile = 8192 B; stage = Ahi|Alo|Bhi|Blo = 32768 B; 3 stages = 100352 B total
// -> 2 CTAs/SM (200704 <= 228KB carveout).
#define SM_TOKS 0
#define SM_WLS  512
#define SM_BIAS 1024
#define SM_BUF  2048
#define TILE_B   8192
#define STAGE_B  32768
#define OFF_ALO  TILE_B
#define OFF_BHI  (2 * TILE_B)
#define OFF_BLO  (3 * TILE_B)
#define SMEM_BYTES (SM_BUF + 3 * STAGE_B)

// ---------------- gate + x split (fused) ----------------
__global__ void gate_kernel(const float* __restrict__ x, const float* __restrict__ Wg) {
    int t = blockIdx.x;
    int tid = threadIdx.x;  // 256 threads, 4 cols each
    float4 v = ((const float4*)(x + (size_t)t * D_DIM))[tid];
    float vv[4] = {v.x, v.y, v.z, v.w};

    uint32_t ph[2], pl[2];
#pragma unroll
    for (int j = 0; j < 4; j++) {
        __nv_bfloat16 hb = __float2bfloat16(vv[j]);
        __nv_bfloat16 lb = __float2bfloat16(vv[j] - __bfloat162float(hb));
        uint32_t hbits = (uint32_t)__bfloat16_as_ushort(hb);
        uint32_t lbits = (uint32_t)__bfloat16_as_ushort(lb);
        if (j & 1) { ph[j >> 1] |= hbits << 16; pl[j >> 1] |= lbits << 16; }
        else       { ph[j >> 1]  = hbits;       pl[j >> 1]  = lbits; }
    }
    size_t xo = ((size_t)t * D_DIM + tid * 4) >> 2;
    ((uint2*)g_xhi)[xo] = make_uint2(ph[0], ph[1]);
    ((uint2*)g_xlo)[xo] = make_uint2(pl[0], pl[1]);

    float acc[E_NUM];
#pragma unroll
    for (int e = 0; e < E_NUM; e++) acc[e] = 0.f;
#pragma unroll
    for (int j = 0; j < 4; j++) {
        int d = tid * 4 + j;
        const float4 w0 = *(const float4*)(Wg + (size_t)d * E_NUM);
        const float4 w1 = *(const float4*)(Wg + (size_t)d * E_NUM + 4);
        acc[0] += vv[j] * w0.x; acc[1] += vv[j] * w0.y;
        acc[2] += vv[j] * w0.z; acc[3] += vv[j] * w0.w;
        acc[4] += vv[j] * w1.x; acc[5] += vv[j] * w1.y;
        acc[6] += vv[j] * w1.z; acc[7] += vv[j] * w1.w;
    }

    __shared__ float red[E_NUM][256];
#pragma unroll
    for (int e = 0; e < E_NUM; e++) red[e][tid] = acc[e];
    __syncthreads();
    for (int s = 128; s > 0; s >>= 1) {
        if (tid < s) {
#pragma unroll
            for (int e = 0; e < E_NUM; e++) red[e][tid] += red[e][tid + s];
        }
        __syncthreads();
    }
    if (tid == 0) {
        float v2[E_NUM];
#pragma unroll
        for (int e = 0; e < E_NUM; e++) v2[e] = fmaxf(red[e][0], 0.f);
        int i1 = 0; float m1 = v2[0];
#pragma unroll
        for (int e = 1; e < E_NUM; e++) if (v2[e] > m1) { m1 = v2[e]; i1 = e; }
        int i2 = -1; float m2 = -1e30f;
#pragma unroll
        for (int e = 0; e < E_NUM; e++) if (e != i1 && v2[e] > m2) { m2 = v2[e]; i2 = e; }
        float eb = __expf(m2 - m1);
        float inv = 1.f / (1.f + eb);
        g_sel[t * 2 + 0] = i1;  g_w[t * 2 + 0] = inv;
        g_sel[t * 2 + 1] = i2;  g_w[t * 2 + 1] = eb * inv;
    }
}

// ---------------- per-expert token lists (deterministic scan) ----------------
__global__ void build_lists_kernel() {
    int e = blockIdx.x;
    int tid = threadIdx.x;  // 1024
    __shared__ int ssum[1024];
    int t0 = tid * 4;
    int flag[4]; float wv[4];
    int cnt = 0;
#pragma unroll
    for (int j = 0; j < 4; j++) {
        int t = t0 + j;
        int s0 = g_sel[t * 2], s1 = g_sel[t * 2 + 1];
        flag[j] = 0; wv[j] = 0.f;
        if (s0 == e)      { flag[j] = 1; wv[j] = g_w[t * 2]; }
        else if (s1 == e) { flag[j] = 1; wv[j] = g_w[t * 2 + 1]; }
        cnt += flag[j];
    }
    ssum[tid] = cnt;
    __syncthreads();
    for (int off = 1; off < 1024; off <<= 1) {
        int v = (tid >= off) ? ssum[tid - off] : 0;
        __syncthreads();
        ssum[tid] += v;
        __syncthreads();
    }
    int pos = ssum[tid] - cnt;
#pragma unroll
    for (int j = 0; j < 4; j++) {
        if (flag[j]) {
            g_list[e * N_TOK + pos] = t0 + j;
            g_lw[e * N_TOK + pos] = wv[j];
            pos++;
        }
    }
    if (tid == 1023) g_count[e] = ssum[1023];
}

// ---------------- conversions ----------------
__device__ __forceinline__ void split_bf16(float v, __nv_bfloat16& h, __nv_bfloat16& l) {
    h = __float2bfloat16(v);
    l = __float2bfloat16(v - __bfloat162float(h));
}

__device__ __forceinline__ int slot_base(int e) {
    int b = 0;
#pragma unroll
    for (int i = 0; i < E_NUM; i++) if (i < e) b += g_count[i];
    return b;
}

// in: [e][R][C] fp32 -> out hi/lo: [e][C][R] bf16, packed uint2 stores
__global__ void transpose_split_kernel(const float* __restrict__ in, int which, int R, int C) {
    int e = blockIdx.z;
    const float* src = in + (size_t)e * R * C;
    __nv_bfloat16* ohi = (which ? g_w2hi : g_w1hi) + (size_t)e * R * C;
    __nv_bfloat16* olo = (which ? g_w2lo : g_w1lo) + (size_t)e * R * C;
    __shared__ float t[32][33];
    int tid = threadIdx.x;
    int tx = tid & 31, ty = tid >> 5;
    int c0 = blockIdx.x * 32, r0 = blockIdx.y * 32;
#pragma unroll
    for (int j = 0; j < 4; j++)
        t[ty + 8 * j][tx] = src[(size_t)(r0 + ty + 8 * j) * C + c0 + tx];
    __syncthreads();
    int cc = tid >> 3, g = tid & 7;
    float v0 = t[g * 4 + 0][cc], v1 = t[g * 4 + 1][cc];
    float v2 = t[g * 4 + 2][cc], v3 = t[g * 4 + 3][cc];
    __nv_bfloat16 h0, l0, h1, l1, h2, l2, h3, l3;
    split_bf16(v0, h0, l0); split_bf16(v1, h1, l1);
    split_bf16(v2, h2, l2); split_bf16(v3, h3, l3);
    uint2 uh = make_uint2(
        (uint32_t)__bfloat16_as_ushort(h0) | ((uint32_t)__bfloat16_as_ushort(h1) << 16),
        (uint32_t)__bfloat16_as_ushort(h2) | ((uint32_t)__bfloat16_as_ushort(h3) << 16));
    uint2 ul = make_uint2(
        (uint32_t)__bfloat16_as_ushort(l0) | ((uint32_t)__bfloat16_as_ushort(l1) << 16),
        (uint32_t)__bfloat16_as_ushort(l2) | ((uint32_t)__bfloat16_as_ushort(l3) << 16));
    size_t ob = (size_t)(c0 + cc) * R + r0 + g * 4;
    *(uint2*)(ohi + ob) = uh;
    *(uint2*)(olo + ob) = ul;
}

// =============================================================================
// GEMM1: h[slot] = relu(x[tok] @ W1t[e]^T + b1[e])   (hi/lo bf16 out)
// CTA tile 128x128, BK=32, 8 warps, swizzled smem, 3-stage ring w/ 1 sync/iter
// =============================================================================
__global__ void __launch_bounds__(256, 2) ffn1_kernel(const float* __restrict__ b1) {
    int e = blockIdx.z;
    int cnt = g_count[e];
    int rowTile = blockIdx.y * 128;
    if (rowTile >= cnt) return;
    int sbase = slot_base(e);
    int colTile = blockIdx.x * 128;

    extern __shared__ char sm[];
    uint32_t sb = smem_u32(sm);
    int tid = threadIdx.x;
    int*   toksS = (int*)(sm + SM_TOKS);
    float* biasS = (float*)(sm + SM_BIAS);

    if (tid < 128) {
        int r = rowTile + tid;
        toksS[tid] = (r < cnt) ? g_list[e * N_TOK + r] : 0;
        biasS[tid] = b1[(size_t)e * H_DIM + colTile + tid];
    }
    __syncthreads();

    const int NIT = D_DIM / 32;  // 32

    auto load_stage = [&](int p, int it) {
        int k0 = it * 32;
        uint32_t base = sb + SM_BUF + p * STAGE_B;
#pragma unroll
        for (int j = 0; j < 8; j++) {
            int idx = j * 256 + tid;
            int tile = idx >> 9, v = idx & 511, row = v >> 2, ch = v & 3;
            uint32_t dst = base + tile * TILE_B + row * 64 + (((ch ^ (row >> 1)) & 3) << 4);
            const __nv_bfloat16* src;
            if (tile == 0)      src = g_xhi + (size_t)toksS[row] * D_DIM + k0 + ch * 8;
            else if (tile == 1) src = g_xlo + (size_t)toksS[row] * D_DIM + k0 + ch * 8;
            else if (tile == 2) src = g_w1hi + (size_t)(e * H_DIM + colTile + row) * D_DIM + k0 + ch * 8;
            else                src = g_w1lo + (size_t)(e * H_DIM + colTile + row) * D_DIM + k0 + ch * 8;
            CPASYNC16(dst, src);
        }
    };

    int lane = tid & 31, w = tid >> 5;
    int wm = w & 3, wn = w >> 2;
    int aRow0 = wm * 32 + (lane & 15), aRow1 = aRow0 + 16;
    uint32_t aB0 = aRow0 * 64, aB1 = aRow1 * 64;
    int aS0 = (aRow0 >> 1) & 3, aS1 = (aRow1 >> 1) & 3;
    int cA0 = lane >> 4;
    uint32_t bB[4]; int bS[4];
#pragma unroll
    for (int np = 0; np < 4; np++) {
        int n = wn * 64 + np * 16 + (lane & 7) + ((lane & 16) ? 8 : 0);
        bB[np] = n * 64; bS[np] = (n >> 1) & 3;
    }
    int cB0 = (lane >> 3) & 1;

    float c[64];
#pragma unroll
    for (int i = 0; i < 64; i++) c[i] = 0.f;

    load_stage(0, 0); CP_COMMIT();
    load_stage(1, 1); CP_COMMIT();

    int p = 0, pw = 2;
    for (int it = 0; it < NIT; it++) {
        CP_WAIT1();
        __syncthreads();
        uint32_t base = sb + SM_BUF + p * STAGE_B;
#pragma unroll
        for (int ks = 0; ks < 2; ks++) {
            int cA = cA0 + 2 * ks, cB = cB0 + 2 * ks;
            uint32_t a0 = base + aB0 + (((cA ^ aS0) & 3) << 4);
            uint32_t a1 = base + aB1 + (((cA ^ aS1) & 3) << 4);
            uint32_t ah[8], al[8], bh[16], bl[16];
            LDSM4(ah + 0, a0);
            LDSM4(ah + 4, a1);
            LDSM4(al + 0, a0 + OFF_ALO);
            LDSM4(al + 4, a1 + OFF_ALO);
#pragma unroll
            for (int np = 0; np < 4; np++) {
                uint32_t bb = base + bB[np] + (((cB ^ bS[np]) & 3) << 4);
                LDSM4(bh + np * 4, bb + OFF_BHI);
                LDSM4(bl + np * 4, bb + OFF_BLO);
            }
#pragma unroll
            for (int mi = 0; mi < 2; mi++)
#pragma unroll
                for (int nb = 0; nb < 8; nb++) {
                    float* cc = c + (mi * 8 + nb) * 4;
                    int bi = (nb >> 1) * 4 + (nb & 1) * 2;
                    MMA16816(cc, (mi ? ah + 4 : ah), bh[bi], bh[bi + 1]);
                    MMA16816(cc, (mi ? ah + 4 : ah), bl[bi], bl[bi + 1]);
                    MMA16816(cc, (mi ? al + 4 : al), bh[bi], bh[bi + 1]);
                }
        }
        if (it + 2 < NIT) load_stage(pw, it + 2);
        CP_COMMIT();
        p = (p == 2) ? 0 : p + 1;
        pw = (pw == 2) ? 0 : pw + 1;
    }

    int g = lane >> 2, tq = lane & 3;
#pragma unroll
    for (int mi = 0; mi < 2; mi++)
#pragma unroll
        for (int half = 0; half < 2; half++) {
            int rloc = wm * 32 + mi * 16 + half * 8 + g;
            if (rowTile + rloc >= cnt) continue;
            size_t hb = ((size_t)(sbase + rowTile + rloc)) * H_DIM + colTile;
#pragma unroll
            for (int nb = 0; nb < 8; nb++) {
                int col = wn * 64 + nb * 8 + tq * 2;
                float v0 = fmaxf(c[(mi * 8 + nb) * 4 + half * 2 + 0] + biasS[col], 0.f);
                float v1 = fmaxf(c[(mi * 8 + nb) * 4 + half * 2 + 1] + biasS[col + 1], 0.f);
                __nv_bfloat16 h0, l0, h1, l1;
                split_bf16(v0, h0, l0); split_bf16(v1, h1, l1);
                *(uint32_t*)(g_hhi + hb + col) =
                    (uint32_t)__bfloat16_as_ushort(h0) | ((uint32_t)__bfloat16_as_ushort(h1) << 16);
                *(uint32_t*)(g_hlo + hb + col) =
                    (uint32_t)__bfloat16_as_ushort(l0) | ((uint32_t)__bfloat16_as_ushort(l1) << 16);
            }
        }
}

// =============================================================================
// GEMM2: out[tok] += w * relu(h[slot] @ W2t[e]^T + b2[e])   (same pipeline)
// =============================================================================
__global__ void __launch_bounds__(256, 2) ffn2_kernel(const float* __restrict__ b2,
                                                      float* __restrict__ out) {
    int e = blockIdx.z;
    int cnt = g_count[e];
    int rowTile = blockIdx.y * 128;
    if (rowTile >= cnt) return;
    int sbase = slot_base(e);
    int colTile = blockIdx.x * 128;

    extern __shared__ char sm[];
    uint32_t sb = smem_u32(sm);
    int tid = threadIdx.x;
    int*   toksS = (int*)(sm + SM_TOKS);
    float* wlsS  = (float*)(sm + SM_WLS);
    float* biasS = (float*)(sm + SM_BIAS);

    if (tid < 128) {
        int r = rowTile + tid;
        bool v = (r < cnt);
        toksS[tid] = v ? g_list[e * N_TOK + r] : 0;
        wlsS[tid]  = v ? g_lw[e * N_TOK + r] : 0.f;
        biasS[tid] = b2[(size_t)e * O_DIM + colTile + tid];
    }
    __syncthreads();

    const int NIT = H_DIM / 32;  // 128

    auto load_stage = [&](int p, int it) {
        int k0 = it * 32;
        uint32_t base = sb + SM_BUF + p * STAGE_B;
#pragma unroll
        for (int j = 0; j < 8; j++) {
            int idx = j * 256 + tid;
            int tile = idx >> 9, v = idx & 511, row = v >> 2, ch = v & 3;
            uint32_t dst = base + tile * TILE_B + row * 64 + (((ch ^ (row >> 1)) & 3) << 4);
            const __nv_bfloat16* src;
            int arow = sbase + rowTile + row;
            if (arow >= sbase + cnt) arow = sbase;   // clamp (weight 0 in epilogue)
            if (tile == 0)      src = g_hhi + (size_t)arow * H_DIM + k0 + ch * 8;
            else if (tile == 1) src = g_hlo + (size_t)arow * H_DIM + k0 + ch * 8;
            else if (tile == 2) src = g_w2hi + (size_t)(e * O_DIM + colTile + row) * H_DIM + k0 + ch * 8;
            else                src = g_w2lo + (size_t)(e * O_DIM + colTile + row) * H_DIM + k0 + ch * 8;
            CPASYNC16(dst, src);
        }
    };

    int lane = tid & 31, w = tid >> 5;
    int wm = w & 3, wn = w >> 2;
    int aRow0 = wm * 32 + (lane & 15), aRow1 = aRow0 + 16;
    uint32_t aB0 = aRow0 * 64, aB1 = aRow1 * 64;
    int aS0 = (aRow0 >> 1) & 3, aS1 = (aRow1 >> 1) & 3;
    int cA0 = lane >> 4;
    uint32_t bB[4]; int bS[4];
#pragma unroll
    for (int np = 0; np < 4; np++) {
        int n = wn * 64 + np * 16 + (lane & 7) + ((lane & 16) ? 8 : 0);
        bB[np] = n * 64; bS[np] = (n >> 1) & 3;
    }
    int cB0 = (lane >> 3) & 1;

    float c[64];
#pragma unroll
    for (int i = 0; i < 64; i++) c[i] = 0.f;

    load_stage(0, 0); CP_COMMIT();
    load_stage(1, 1); CP_COMMIT();

    int p = 0, pw = 2;
    for (int it = 0; it < NIT; it++) {
        CP_WAIT1();
        __syncthreads();
        uint32_t base = sb + SM_BUF + p * STAGE_B;
#pragma unroll
        for (int ks = 0; ks < 2; ks++) {
            int cA = cA0 + 2 * ks, cB = cB0 + 2 * ks;
            uint32_t a0 = base + aB0 + (((cA ^ aS0) & 3) << 4);
            uint32_t a1 = base + aB1 + (((cA ^ aS1) & 3) << 4);
            uint32_t ah[8], al[8], bh[16], bl[16];
            LDSM4(ah + 0, a0);
            LDSM4(ah + 4, a1);
            LDSM4(al + 0, a0 + OFF_ALO);
            LDSM4(al + 4, a1 + OFF_ALO);
#pragma unroll
            for (int np = 0; np < 4; np++) {
                uint32_t bb = base + bB[np] + (((cB ^ bS[np]) & 3) << 4);
                LDSM4(bh + np * 4, bb + OFF_BHI);
                LDSM4(bl + np * 4, bb + OFF_BLO);
            }
#pragma unroll
            for (int mi = 0; mi < 2; mi++)
#pragma unroll
                for (int nb = 0; nb < 8; nb++) {
                    float* cc = c + (mi * 8 + nb) * 4;
                    int bi = (nb >> 1) * 4 + (nb & 1) * 2;
                    MMA16816(cc, (mi ? ah + 4 : ah), bh[bi], bh[bi + 1]);
                    MMA16816(cc, (mi ? ah + 4 : ah), bl[bi], bl[bi + 1]);
                    MMA16816(cc, (mi ? al + 4 : al), bh[bi], bh[bi + 1]);
                }
        }
        if (it + 2 < NIT) load_stage(pw, it + 2);
        CP_COMMIT();
        p = (p == 2) ? 0 : p + 1;
        pw = (pw == 2) ? 0 : pw + 1;
    }

    int g = lane >> 2, tq = lane & 3;
#pragma unroll
    for (int mi = 0; mi < 2; mi++)
#pragma unroll
        for (int half = 0; half < 2; half++) {
            int rloc = wm * 32 + mi * 16 + half * 8 + g;
            if (rowTile + rloc >= cnt) continue;
            int tok = toksS[rloc];
            float wc = wlsS[rloc];
            float* orow = out + (size_t)tok * O_DIM + colTile;
#pragma unroll
            for (int nb = 0; nb < 8; nb++) {
                int col = wn * 64 + nb * 8 + tq * 2;
                float v0 = fmaxf(c[(mi * 8 + nb) * 4 + half * 2 + 0] + biasS[col], 0.f) * wc;
                float v1 = fmaxf(c[(mi * 8 + nb) * 4 + half * 2 + 1] + biasS[col + 1], 0.f) * wc;
                atomicAdd(orow + col, v0);
                atomicAdd(orow + col + 1, v1);
            }
        }
}

// ---------------- host ----------------
extern "C" void kernel_launch(void* const* d_in, const int* in_sizes, int n_in,
                              void* d_out, int out_size) {
    const float* x  = (const float*)d_in[0];
    const float* Wg = (const float*)d_in[1];
    const float* W1 = (const float*)d_in[2];
    const float* b1 = (const float*)d_in[3];
    const float* W2 = (const float*)d_in[4];
    const float* b2 = (const float*)d_in[5];
    float* out = (float*)d_out;

    cudaFuncSetAttribute(ffn1_kernel, cudaFuncAttributeMaxDynamicSharedMemorySize, SMEM_BYTES);
    cudaFuncSetAttribute(ffn2_kernel, cudaFuncAttributeMaxDynamicSharedMemorySize, SMEM_BYTES);

    // ncu captures the 4th kernel launch -> ffn1.
    transpose_split_kernel<<<dim3(H_DIM / 32, D_DIM / 32, E_NUM), 256>>>(W1, 0, D_DIM, H_DIM);
    gate_kernel<<<N_TOK, 256>>>(x, Wg);
    build_lists_kernel<<<E_NUM, 1024>>>();
    ffn1_kernel<<<dim3(H_DIM / 128, N_TOK / 128, E_NUM), 256, SMEM_BYTES>>>(b1);
    transpose_split_kernel<<<dim3(O_DIM / 32, H_DIM / 32, E_NUM), 256>>>(W2, 1, H_DIM, O_DIM);
    cudaMemsetAsync(out, 0, (size_t)N_TOK * O_DIM * sizeof(float), 0);
    ffn2_kernel<<<dim3(O_DIM / 128, N_TOK / 128, E_NUM), 256, SMEM_BYTES>>>(b2, out);
}

// round 12
// speedup vs baseline: 1.9205x; 1.3801x over previous
#include <cuda_runtime.h>
#include <cuda_fp16.h>
#include <stdint.h>
#include <math.h>

#define N_TOK 4096
#define D_DIM 1024
#define H_DIM 4096
#define O_DIM 1024
#define E_NUM 8

// ---------------- static device scratch ----------------
__device__ __half g_xhi[(size_t)N_TOK * D_DIM];
__device__ __half g_xlo[(size_t)N_TOK * D_DIM];
__device__ __half g_w1[(size_t)E_NUM * H_DIM * D_DIM];   // [e][h][d] (transposed, single fp16)
__device__ __half g_w2[(size_t)E_NUM * O_DIM * H_DIM];   // [e][o][h] (transposed, single fp16)
__device__ __half g_hhi[(size_t)2 * N_TOK * H_DIM];      // compact slots
__device__ __half g_hlo[(size_t)2 * N_TOK * H_DIM];
__device__ int   g_sel[N_TOK * 2];
__device__ float g_w[N_TOK * 2];
__device__ int   g_list[E_NUM * N_TOK];
__device__ float g_lw[E_NUM * N_TOK];
__device__ int   g_count[E_NUM];

// ---------------- PTX helpers (sm_80-baseline only) ----------------
__device__ __forceinline__ uint32_t smem_u32(const void* p) {
    uint32_t a;
    asm("{ .reg .u64 t; cvta.to.shared.u64 t, %1; cvt.u32.u64 %0, t; }" : "=r"(a) : "l"(p));
    return a;
}

#define CPASYNC16(dst, src) \
    asm volatile("cp.async.cg.shared.global [%0], [%1], 16;" :: "r"(dst), "l"(src))
#define CP_COMMIT() asm volatile("cp.async.commit_group;" ::: "memory")
#define CP_WAIT2()  asm volatile("cp.async.wait_group 2;" ::: "memory")

#define LDSM4(r, a) \
    asm volatile("ldmatrix.sync.aligned.m8n8.x4.shared.b16 {%0,%1,%2,%3}, [%4];" \
                 : "=r"((r)[0]), "=r"((r)[1]), "=r"((r)[2]), "=r"((r)[3]) : "r"(a))

#define MMAH(c, a, b0, b1) \
    asm volatile("mma.sync.aligned.m16n8k16.row.col.f32.f16.f16.f32 " \
                 "{%0,%1,%2,%3}, {%4,%5,%6,%7}, {%8,%9}, {%0,%1,%2,%3};" \
                 : "+f"((c)[0]), "+f"((c)[1]), "+f"((c)[2]), "+f"((c)[3]) \
                 : "r"((a)[0]), "r"((a)[1]), "r"((a)[2]), "r"((a)[3]), "r"(b0), "r"(b1))

// ---------------- smem layout ----------------
// Swizzled tiles: 128 rows x 64 B, chunk c at byte (((c ^ ((row>>1)&3)) & 3) * 16).
// tile = 8192 B; stage = Ahi|Alo|B = 24576 B; 4 stages = 100352 B total
// -> 2 CTAs/SM (200704 <= 228KB carveout), prefetch distance 3.
#define SM_TOKS 0
#define SM_WLS  512
#define SM_BIAS 1024
#define SM_BUF  2048
#define TILE_B   8192
#define STAGE_B  24576
#define OFF_ALO  TILE_B
#define OFF_B    (2 * TILE_B)
#define NSTAGE   4
#define SMEM_BYTES (SM_BUF + NSTAGE * STAGE_B)

__device__ __forceinline__ void split_h16(float v, __half& h, __half& l) {
    h = __float2half_rn(v);
    l = __float2half_rn(v - __half2float(h));
}

// ---------------- gate + x split (fused) ----------------
__global__ void gate_kernel(const float* __restrict__ x, const float* __restrict__ Wg) {
    int t = blockIdx.x;
    int tid = threadIdx.x;  // 256 threads, 4 cols each
    float4 v = ((const float4*)(x + (size_t)t * D_DIM))[tid];
    float vv[4] = {v.x, v.y, v.z, v.w};

    uint32_t ph[2], pl[2];
#pragma unroll
    for (int j = 0; j < 4; j++) {
        __half hb, lb; split_h16(vv[j], hb, lb);
        uint32_t hbits = (uint32_t)__half_as_ushort(hb);
        uint32_t lbits = (uint32_t)__half_as_ushort(lb);
        if (j & 1) { ph[j >> 1] |= hbits << 16; pl[j >> 1] |= lbits << 16; }
        else       { ph[j >> 1]  = hbits;       pl[j >> 1]  = lbits; }
    }
    size_t xo = ((size_t)t * D_DIM + tid * 4) >> 2;
    ((uint2*)g_xhi)[xo] = make_uint2(ph[0], ph[1]);
    ((uint2*)g_xlo)[xo] = make_uint2(pl[0], pl[1]);

    float acc[E_NUM];
#pragma unroll
    for (int e = 0; e < E_NUM; e++) acc[e] = 0.f;
#pragma unroll
    for (int j = 0; j < 4; j++) {
        int d = tid * 4 + j;
        const float4 w0 = *(const float4*)(Wg + (size_t)d * E_NUM);
        const float4 w1 = *(const float4*)(Wg + (size_t)d * E_NUM + 4);
        acc[0] += vv[j] * w0.x; acc[1] += vv[j] * w0.y;
        acc[2] += vv[j] * w0.z; acc[3] += vv[j] * w0.w;
        acc[4] += vv[j] * w1.x; acc[5] += vv[j] * w1.y;
        acc[6] += vv[j] * w1.z; acc[7] += vv[j] * w1.w;
    }

    __shared__ float red[E_NUM][256];
#pragma unroll
    for (int e = 0; e < E_NUM; e++) red[e][tid] = acc[e];
    __syncthreads();
    for (int s = 128; s > 0; s >>= 1) {
        if (tid < s) {
#pragma unroll
            for (int e = 0; e < E_NUM; e++) red[e][tid] += red[e][tid + s];
        }
        __syncthreads();
    }
    if (tid == 0) {
        float v2[E_NUM];
#pragma unroll
        for (int e = 0; e < E_NUM; e++) v2[e] = fmaxf(red[e][0], 0.f);
        int i1 = 0; float m1 = v2[0];
#pragma unroll
        for (int e = 1; e < E_NUM; e++) if (v2[e] > m1) { m1 = v2[e]; i1 = e; }
        int i2 = -1; float m2 = -1e30f;
#pragma unroll
        for (int e = 0; e < E_NUM; e++) if (e != i1 && v2[e] > m2) { m2 = v2[e]; i2 = e; }
        float eb = __expf(m2 - m1);
        float inv = 1.f / (1.f + eb);
        g_sel[t * 2 + 0] = i1;  g_w[t * 2 + 0] = inv;
        g_sel[t * 2 + 1] = i2;  g_w[t * 2 + 1] = eb * inv;
    }
}

// ---------------- per-expert token lists (deterministic scan) ----------------
__global__ void build_lists_kernel() {
    int e = blockIdx.x;
    int tid = threadIdx.x;  // 1024
    __shared__ int ssum[1024];
    int t0 = tid * 4;
    int flag[4]; float wv[4];
    int cnt = 0;
#pragma unroll
    for (int j = 0; j < 4; j++) {
        int t = t0 + j;
        int s0 = g_sel[t * 2], s1 = g_sel[t * 2 + 1];
        flag[j] = 0; wv[j] = 0.f;
        if (s0 == e)      { flag[j] = 1; wv[j] = g_w[t * 2]; }
        else if (s1 == e) { flag[j] = 1; wv[j] = g_w[t * 2 + 1]; }
        cnt += flag[j];
    }
    ssum[tid] = cnt;
    __syncthreads();
    for (int off = 1; off < 1024; off <<= 1) {
        int v = (tid >= off) ? ssum[tid - off] : 0;
        __syncthreads();
        ssum[tid] += v;
        __syncthreads();
    }
    int pos = ssum[tid] - cnt;
#pragma unroll
    for (int j = 0; j < 4; j++) {
        if (flag[j]) {
            g_list[e * N_TOK + pos] = t0 + j;
            g_lw[e * N_TOK + pos] = wv[j];
            pos++;
        }
    }
    if (tid == 1023) g_count[e] = ssum[1023];
}

__device__ __forceinline__ int slot_base(int e) {
    int b = 0;
#pragma unroll
    for (int i = 0; i < E_NUM; i++) if (i < e) b += g_count[i];
    return b;
}

// in: [e][R][C] fp32 -> out: [e][C][R] fp16, selected INSIDE device code
// (passing a __device__ symbol as a kernel arg from host is invalid — R11 bug)
__global__ void transpose_cvt_kernel(const float* __restrict__ in, int which, int R, int C) {
    int e = blockIdx.z;
    const float* src = in + (size_t)e * R * C;
    __half* o = (which ? g_w2 : g_w1) + (size_t)e * R * C;
    __shared__ float t[32][33];
    int tid = threadIdx.x;
    int tx = tid & 31, ty = tid >> 5;
    int c0 = blockIdx.x * 32, r0 = blockIdx.y * 32;
#pragma unroll
    for (int j = 0; j < 4; j++)
        t[ty + 8 * j][tx] = src[(size_t)(r0 + ty + 8 * j) * C + c0 + tx];
    __syncthreads();
    int cc = tid >> 3, g = tid & 7;
    __half h0 = __float2half_rn(t[g * 4 + 0][cc]);
    __half h1 = __float2half_rn(t[g * 4 + 1][cc]);
    __half h2 = __float2half_rn(t[g * 4 + 2][cc]);
    __half h3 = __float2half_rn(t[g * 4 + 3][cc]);
    uint2 uh = make_uint2(
        (uint32_t)__half_as_ushort(h0) | ((uint32_t)__half_as_ushort(h1) << 16),
        (uint32_t)__half_as_ushort(h2) | ((uint32_t)__half_as_ushort(h3) << 16));
    size_t ob = (size_t)(c0 + cc) * R + r0 + g * 4;
    *(uint2*)(o + ob) = uh;
}

// =============================================================================
// GEMM1: h[slot] = relu(x[tok] @ W1t[e]^T + b1[e])
// A = x fp16 hi/lo (2 products), B = W1 single fp16. 4-stage ring, 1 sync/iter.
// =============================================================================
__global__ void __launch_bounds__(256, 2) ffn1_kernel(const float* __restrict__ b1) {
    int e = blockIdx.z;
    int cnt = g_count[e];
    int rowTile = blockIdx.y * 128;
    if (rowTile >= cnt) return;
    int sbase = slot_base(e);
    int colTile = blockIdx.x * 128;

    extern __shared__ char sm[];
    uint32_t sb = smem_u32(sm);
    int tid = threadIdx.x;
    int*   toksS = (int*)(sm + SM_TOKS);
    float* biasS = (float*)(sm + SM_BIAS);

    if (tid < 128) {
        int r = rowTile + tid;
        toksS[tid] = (r < cnt) ? g_list[e * N_TOK + r] : 0;
        biasS[tid] = b1[(size_t)e * H_DIM + colTile + tid];
    }
    __syncthreads();

    const int NIT = D_DIM / 32;  // 32

    auto load_stage = [&](int p, int it) {
        int k0 = it * 32;
        uint32_t base = sb + SM_BUF + p * STAGE_B;
#pragma unroll
        for (int j = 0; j < 6; j++) {
            int idx = j * 256 + tid;  // 1536 chunks: Ahi 512 | Alo 512 | B 512
            int tile = idx >> 9, v = idx & 511, row = v >> 2, ch = v & 3;
            uint32_t dst = base + tile * TILE_B + row * 64 + (((ch ^ (row >> 1)) & 3) << 4);
            const __half* src;
            if (tile == 0)      src = g_xhi + (size_t)toksS[row] * D_DIM + k0 + ch * 8;
            else if (tile == 1) src = g_xlo + (size_t)toksS[row] * D_DIM + k0 + ch * 8;
            else                src = g_w1 + (size_t)(e * H_DIM + colTile + row) * D_DIM + k0 + ch * 8;
            CPASYNC16(dst, src);
        }
    };

    int lane = tid & 31, w = tid >> 5;
    int wm = w & 3, wn = w >> 2;
    int aRow0 = wm * 32 + (lane & 15), aRow1 = aRow0 + 16;
    uint32_t aB0 = aRow0 * 64, aB1 = aRow1 * 64;
    int aS0 = (aRow0 >> 1) & 3, aS1 = (aRow1 >> 1) & 3;
    int cA0 = lane >> 4;
    uint32_t bB[4]; int bS[4];
#pragma unroll
    for (int np = 0; np < 4; np++) {
        int n = wn * 64 + np * 16 + (lane & 7) + ((lane & 16) ? 8 : 0);
        bB[np] = n * 64; bS[np] = (n >> 1) & 3;
    }
    int cB0 = (lane >> 3) & 1;

    float c[64];
#pragma unroll
    for (int i = 0; i < 64; i++) c[i] = 0.f;

    load_stage(0, 0); CP_COMMIT();
    load_stage(1, 1); CP_COMMIT();
    load_stage(2, 2); CP_COMMIT();

    int p = 0, pw = 3;
    for (int it = 0; it < NIT; it++) {
        CP_WAIT2();
        __syncthreads();
        uint32_t base = sb + SM_BUF + p * STAGE_B;
#pragma unroll
        for (int ks = 0; ks < 2; ks++) {
            int cA = cA0 + 2 * ks, cB = cB0 + 2 * ks;
            uint32_t a0 = base + aB0 + (((cA ^ aS0) & 3) << 4);
            uint32_t a1 = base + aB1 + (((cA ^ aS1) & 3) << 4);
            uint32_t ah[8], al[8], bh[16];
            LDSM4(ah + 0, a0);
            LDSM4(ah + 4, a1);
            LDSM4(al + 0, a0 + OFF_ALO);
            LDSM4(al + 4, a1 + OFF_ALO);
#pragma unroll
            for (int np = 0; np < 4; np++) {
                uint32_t bb = base + bB[np] + (((cB ^ bS[np]) & 3) << 4);
                LDSM4(bh + np * 4, bb + OFF_B);
            }
#pragma unroll
            for (int mi = 0; mi < 2; mi++)
#pragma unroll
                for (int nb = 0; nb < 8; nb++) {
                    float* cc = c + (mi * 8 + nb) * 4;
                    int bi = (nb >> 1) * 4 + (nb & 1) * 2;
                    MMAH(cc, (mi ? ah + 4 : ah), bh[bi], bh[bi + 1]);
                    MMAH(cc, (mi ? al + 4 : al), bh[bi], bh[bi + 1]);
                }
        }
        if (it + 3 < NIT) load_stage(pw, it + 3);
        CP_COMMIT();
        p = (p == NSTAGE - 1) ? 0 : p + 1;
        pw = (pw == NSTAGE - 1) ? 0 : pw + 1;
    }

    int g = lane >> 2, tq = lane & 3;
#pragma unroll
    for (int mi = 0; mi < 2; mi++)
#pragma unroll
        for (int half = 0; half < 2; half++) {
            int rloc = wm * 32 + mi * 16 + half * 8 + g;
            if (rowTile + rloc >= cnt) continue;
            size_t hb = ((size_t)(sbase + rowTile + rloc)) * H_DIM + colTile;
#pragma unroll
            for (int nb = 0; nb < 8; nb++) {
                int col = wn * 64 + nb * 8 + tq * 2;
                float v0 = fmaxf(c[(mi * 8 + nb) * 4 + half * 2 + 0] + biasS[col], 0.f);
                float v1 = fmaxf(c[(mi * 8 + nb) * 4 + half * 2 + 1] + biasS[col + 1], 0.f);
                __half h0, l0, h1, l1;
                split_h16(v0, h0, l0); split_h16(v1, h1, l1);
                *(uint32_t*)(g_hhi + hb + col) =
                    (uint32_t)__half_as_ushort(h0) | ((uint32_t)__half_as_ushort(h1) << 16);
                *(uint32_t*)(g_hlo + hb + col) =
                    (uint32_t)__half_as_ushort(l0) | ((uint32_t)__half_as_ushort(l1) << 16);
            }
        }
}

// =============================================================================
// GEMM2: out[tok] += w * relu(h[slot] @ W2t[e]^T + b2[e])   (same pipeline)
// =============================================================================
__global__ void __launch_bounds__(256, 2) ffn2_kernel(const float* __restrict__ b2,
                                                      float* __restrict__ out) {
    int e = blockIdx.z;
    int cnt = g_count[e];
    int rowTile = blockIdx.y * 128;
    if (rowTile >= cnt) return;
    int sbase = slot_base(e);
    int colTile = blockIdx.x * 128;

    extern __shared__ char sm[];
    uint32_t sb = smem_u32(sm);
    int tid = threadIdx.x;
    int*   toksS = (int*)(sm + SM_TOKS);
    float* wlsS  = (float*)(sm + SM_WLS);
    float* biasS = (float*)(sm + SM_BIAS);

    if (tid < 128) {
        int r = rowTile + tid;
        bool v = (r < cnt);
        toksS[tid] = v ? g_list[e * N_TOK + r] : 0;
        wlsS[tid]  = v ? g_lw[e * N_TOK + r] : 0.f;
        biasS[tid] = b2[(size_t)e * O_DIM + colTile + tid];
    }
    __syncthreads();

    const int NIT = H_DIM / 32;  // 128

    auto load_stage = [&](int p, int it) {
        int k0 = it * 32;
        uint32_t base = sb + SM_BUF + p * STAGE_B;
#pragma unroll
        for (int j = 0; j < 6; j++) {
            int idx = j * 256 + tid;
            int tile = idx >> 9, v = idx & 511, row = v >> 2, ch = v & 3;
            uint32_t dst = base + tile * TILE_B + row * 64 + (((ch ^ (row >> 1)) & 3) << 4);
            const __half* src;
            int arow = sbase + rowTile + row;
            if (arow >= sbase + cnt) arow = sbase;   // clamp (weight 0 in epilogue)
            if (tile == 0)      src = g_hhi + (size_t)arow * H_DIM + k0 + ch * 8;
            else if (tile == 1) src = g_hlo + (size_t)arow * H_DIM + k0 + ch * 8;
            else                src = g_w2 + (size_t)(e * O_DIM + colTile + row) * H_DIM + k0 + ch * 8;
            CPASYNC16(dst, src);
        }
    };

    int lane = tid & 31, w = tid >> 5;
    int wm = w & 3, wn = w >> 2;
    int aRow0 = wm * 32 + (lane & 15), aRow1 = aRow0 + 16;
    uint32_t aB0 = aRow0 * 64, aB1 = aRow1 * 64;
    int aS0 = (aRow0 >> 1) & 3, aS1 = (aRow1 >> 1) & 3;
    int cA0 = lane >> 4;
    uint32_t bB[4]; int bS[4];
#pragma unroll
    for (int np = 0; np < 4; np++) {
        int n = wn * 64 + np * 16 + (lane & 7) + ((lane & 16) ? 8 : 0);
        bB[np] = n * 64; bS[np] = (n >> 1) & 3;
    }
    int cB0 = (lane >> 3) & 1;

    float c[64];
#pragma unroll
    for (int i = 0; i < 64; i++) c[i] = 0.f;

    load_stage(0, 0); CP_COMMIT();
    load_stage(1, 1); CP_COMMIT();
    load_stage(2, 2); CP_COMMIT();

    int p = 0, pw = 3;
    for (int it = 0; it < NIT; it++) {
        CP_WAIT2();
        __syncthreads();
        uint32_t base = sb + SM_BUF + p * STAGE_B;
#pragma unroll
        for (int ks = 0; ks < 2; ks++) {
            int cA = cA0 + 2 * ks, cB = cB0 + 2 * ks;
            uint32_t a0 = base + aB0 + (((cA ^ aS0) & 3) << 4);
            uint32_t a1 = base + aB1 + (((cA ^ aS1) & 3) << 4);
            uint32_t ah[8], al[8], bh[16];
            LDSM4(ah + 0, a0);
            LDSM4(ah + 4, a1);
            LDSM4(al + 0, a0 + OFF_ALO);
            LDSM4(al + 4, a1 + OFF_ALO);
#pragma unroll
            for (int np = 0; np < 4; np++) {
                uint32_t bb = base + bB[np] + (((cB ^ bS[np]) & 3) << 4);
                LDSM4(bh + np * 4, bb + OFF_B);
            }
#pragma unroll
            for (int mi = 0; mi < 2; mi++)
#pragma unroll
                for (int nb = 0; nb < 8; nb++) {
                    float* cc = c + (mi * 8 + nb) * 4;
                    int bi = (nb >> 1) * 4 + (nb & 1) * 2;
                    MMAH(cc, (mi ? ah + 4 : ah), bh[bi], bh[bi + 1]);
                    MMAH(cc, (mi ? al + 4 : al), bh[bi], bh[bi + 1]);
                }
        }
        if (it + 3 < NIT) load_stage(pw, it + 3);
        CP_COMMIT();
        p = (p == NSTAGE - 1) ? 0 : p + 1;
        pw = (pw == NSTAGE - 1) ? 0 : pw + 1;
    }

    int g = lane >> 2, tq = lane & 3;
#pragma unroll
    for (int mi = 0; mi < 2; mi++)
#pragma unroll
        for (int half = 0; half < 2; half++) {
            int rloc = wm * 32 + mi * 16 + half * 8 + g;
            if (rowTile + rloc >= cnt) continue;
            int tok = toksS[rloc];
            float wc = wlsS[rloc];
            float* orow = out + (size_t)tok * O_DIM + colTile;
#pragma unroll
            for (int nb = 0; nb < 8; nb++) {
                int col = wn * 64 + nb * 8 + tq * 2;
                float v0 = fmaxf(c[(mi * 8 + nb) * 4 + half * 2 + 0] + biasS[col], 0.f) * wc;
                float v1 = fmaxf(c[(mi * 8 + nb) * 4 + half * 2 + 1] + biasS[col + 1], 0.f) * wc;
                atomicAdd(orow + col, v0);
                atomicAdd(orow + col + 1, v1);
            }
        }
}

// ---------------- host ----------------
extern "C" void kernel_launch(void* const* d_in, const int* in_sizes, int n_in,
                              void* d_out, int out_size) {
    const float* x  = (const float*)d_in[0];
    const float* Wg = (const float*)d_in[1];
    const float* W1 = (const float*)d_in[2];
    const float* b1 = (const float*)d_in[3];
    const float* W2 = (const float*)d_in[4];
    const float* b2 = (const float*)d_in[5];
    float* out = (float*)d_out;

    cudaFuncSetAttribute(ffn1_kernel, cudaFuncAttributeMaxDynamicSharedMemorySize, SMEM_BYTES);
    cudaFuncSetAttribute(ffn2_kernel, cudaFuncAttributeMaxDynamicSharedMemorySize, SMEM_BYTES);

    // ncu captures the 4th kernel launch -> ffn1.
    transpose_cvt_kernel<<<dim3(H_DIM / 32, D_DIM / 32, E_NUM), 256>>>(W1, 0, D_DIM, H_DIM);
    gate_kernel<<<N_TOK, 256>>>(x, Wg);
    build_lists_kernel<<<E_NUM, 1024>>>();
    ffn1_kernel<<<dim3(H_DIM / 128, N_TOK / 128, E_NUM), 256, SMEM_BYTES>>>(b1);
    transpose_cvt_kernel<<<dim3(O_DIM / 32, H_DIM / 32, E_NUM), 256>>>(W2, 1, H_DIM, O_DIM);
    cudaMemsetAsync(out, 0, (size_t)N_TOK * O_DIM * sizeof(float), 0);
    ffn2_kernel<<<dim3(O_DIM / 128, N_TOK / 128, E_NUM), 256, SMEM_BYTES>>>(b2, out);
}

// round 13
// speedup vs baseline: 3.1020x; 1.6152x over previous
#include <cuda_runtime.h>
#include <cuda_fp16.h>
#include <stdint.h>
#include <math.h>

#define N_TOK 4096
#define D_DIM 1024
#define H_DIM 4096
#define O_DIM 1024
#define E_NUM 8

// ---------------- static device scratch ----------------
__device__ __half g_x[(size_t)N_TOK * D_DIM];            // x fp16
__device__ __half g_w1[(size_t)E_NUM * H_DIM * D_DIM];   // [e][h][d] (transposed fp16)
__device__ __half g_w2[(size_t)E_NUM * O_DIM * H_DIM];   // [e][o][h] (transposed fp16)
__device__ __half g_h[(size_t)2 * N_TOK * H_DIM];        // compact slots fp16
__device__ int   g_sel[N_TOK * 2];
__device__ float g_w[N_TOK * 2];
__device__ int   g_list[E_NUM * N_TOK];
__device__ float g_lw[E_NUM * N_TOK];
__device__ int   g_count[E_NUM];

// ---------------- PTX helpers (sm_80-baseline only) ----------------
__device__ __forceinline__ uint32_t smem_u32(const void* p) {
    uint32_t a;
    asm("{ .reg .u64 t; cvta.to.shared.u64 t, %1; cvt.u32.u64 %0, t; }" : "=r"(a) : "l"(p));
    return a;
}

#define CPASYNC16(dst, src) \
    asm volatile("cp.async.cg.shared.global [%0], [%1], 16;" :: "r"(dst), "l"(src))
#define CP_COMMIT() asm volatile("cp.async.commit_group;" ::: "memory")
#define CP_WAIT2()  asm volatile("cp.async.wait_group 2;" ::: "memory")

#define LDSM4(r, a) \
    asm volatile("ldmatrix.sync.aligned.m8n8.x4.shared.b16 {%0,%1,%2,%3}, [%4];" \
                 : "=r"((r)[0]), "=r"((r)[1]), "=r"((r)[2]), "=r"((r)[3]) : "r"(a))

#define MMAH(c, a, b0, b1) \
    asm volatile("mma.sync.aligned.m16n8k16.row.col.f32.f16.f16.f32 " \
                 "{%0,%1,%2,%3}, {%4,%5,%6,%7}, {%8,%9}, {%0,%1,%2,%3};" \
                 : "+f"((c)[0]), "+f"((c)[1]), "+f"((c)[2]), "+f"((c)[3]) \
                 : "r"((a)[0]), "r"((a)[1]), "r"((a)[2]), "r"((a)[3]), "r"(b0), "r"(b1))

// ---------------- smem layout ----------------
// Swizzled tiles: 128 rows x 64 B, chunk c at byte (((c ^ ((row>>1)&3)) & 3) * 16).
// tile = 8192 B; stage = A | B = 16384 B; 4 stages = 67584 B total
// -> 2 CTAs/SM, prefetch distance 3 (wait_group 2).
#define SM_TOKS 0
#define SM_WLS  512
#define SM_BIAS 1024
#define SM_BUF  2048
#define TILE_B   8192
#define STAGE_B  16384
#define OFF_B    TILE_B
#define NSTAGE   4
#define SMEM_BYTES (SM_BUF + NSTAGE * STAGE_B)

// ---------------- gate + x convert (fused) ----------------
__global__ void gate_kernel(const float* __restrict__ x, const float* __restrict__ Wg) {
    int t = blockIdx.x;
    int tid = threadIdx.x;  // 256 threads, 4 cols each
    float4 v = ((const float4*)(x + (size_t)t * D_DIM))[tid];
    float vv[4] = {v.x, v.y, v.z, v.w};

    uint32_t ph[2];
#pragma unroll
    for (int j = 0; j < 4; j++) {
        uint32_t hbits = (uint32_t)__half_as_ushort(__float2half_rn(vv[j]));
        if (j & 1) ph[j >> 1] |= hbits << 16;
        else       ph[j >> 1]  = hbits;
    }
    size_t xo = ((size_t)t * D_DIM + tid * 4) >> 2;
    ((uint2*)g_x)[xo] = make_uint2(ph[0], ph[1]);

    float acc[E_NUM];
#pragma unroll
    for (int e = 0; e < E_NUM; e++) acc[e] = 0.f;
#pragma unroll
    for (int j = 0; j < 4; j++) {
        int d = tid * 4 + j;
        const float4 w0 = *(const float4*)(Wg + (size_t)d * E_NUM);
        const float4 w1 = *(const float4*)(Wg + (size_t)d * E_NUM + 4);
        acc[0] += vv[j] * w0.x; acc[1] += vv[j] * w0.y;
        acc[2] += vv[j] * w0.z; acc[3] += vv[j] * w0.w;
        acc[4] += vv[j] * w1.x; acc[5] += vv[j] * w1.y;
        acc[6] += vv[j] * w1.z; acc[7] += vv[j] * w1.w;
    }

    __shared__ float red[E_NUM][256];
#pragma unroll
    for (int e = 0; e < E_NUM; e++) red[e][tid] = acc[e];
    __syncthreads();
    for (int s = 128; s > 0; s >>= 1) {
        if (tid < s) {
#pragma unroll
            for (int e = 0; e < E_NUM; e++) red[e][tid] += red[e][tid + s];
        }
        __syncthreads();
    }
    if (tid == 0) {
        float v2[E_NUM];
#pragma unroll
        for (int e = 0; e < E_NUM; e++) v2[e] = fmaxf(red[e][0], 0.f);
        int i1 = 0; float m1 = v2[0];
#pragma unroll
        for (int e = 1; e < E_NUM; e++) if (v2[e] > m1) { m1 = v2[e]; i1 = e; }
        int i2 = -1; float m2 = -1e30f;
#pragma unroll
        for (int e = 0; e < E_NUM; e++) if (e != i1 && v2[e] > m2) { m2 = v2[e]; i2 = e; }
        float eb = __expf(m2 - m1);
        float inv = 1.f / (1.f + eb);
        g_sel[t * 2 + 0] = i1;  g_w[t * 2 + 0] = inv;
        g_sel[t * 2 + 1] = i2;  g_w[t * 2 + 1] = eb * inv;
    }
}

// ---------------- per-expert token lists (deterministic scan) ----------------
__global__ void build_lists_kernel() {
    int e = blockIdx.x;
    int tid = threadIdx.x;  // 1024
    __shared__ int ssum[1024];
    int t0 = tid * 4;
    int flag[4]; float wv[4];
    int cnt = 0;
#pragma unroll
    for (int j = 0; j < 4; j++) {
        int t = t0 + j;
        int s0 = g_sel[t * 2], s1 = g_sel[t * 2 + 1];
        flag[j] = 0; wv[j] = 0.f;
        if (s0 == e)      { flag[j] = 1; wv[j] = g_w[t * 2]; }
        else if (s1 == e) { flag[j] = 1; wv[j] = g_w[t * 2 + 1]; }
        cnt += flag[j];
    }
    ssum[tid] = cnt;
    __syncthreads();
    for (int off = 1; off < 1024; off <<= 1) {
        int v = (tid >= off) ? ssum[tid - off] : 0;
        __syncthreads();
        ssum[tid] += v;
        __syncthreads();
    }
    int pos = ssum[tid] - cnt;
#pragma unroll
    for (int j = 0; j < 4; j++) {
        if (flag[j]) {
            g_list[e * N_TOK + pos] = t0 + j;
            g_lw[e * N_TOK + pos] = wv[j];
            pos++;
        }
    }
    if (tid == 1023) g_count[e] = ssum[1023];
}

__device__ __forceinline__ int slot_base(int e) {
    int b = 0;
#pragma unroll
    for (int i = 0; i < E_NUM; i++) if (i < e) b += g_count[i];
    return b;
}

// in: [e][R][C] fp32 -> out: [e][C][R] fp16, selected INSIDE device code
__global__ void transpose_cvt_kernel(const float* __restrict__ in, int which, int R, int C) {
    int e = blockIdx.z;
    const float* src = in + (size_t)e * R * C;
    __half* o = (which ? g_w2 : g_w1) + (size_t)e * R * C;
    __shared__ float t[32][33];
    int tid = threadIdx.x;
    int tx = tid & 31, ty = tid >> 5;
    int c0 = blockIdx.x * 32, r0 = blockIdx.y * 32;
#pragma unroll
    for (int j = 0; j < 4; j++)
        t[ty + 8 * j][tx] = src[(size_t)(r0 + ty + 8 * j) * C + c0 + tx];
    __syncthreads();
    int cc = tid >> 3, g = tid & 7;
    __half h0 = __float2half_rn(t[g * 4 + 0][cc]);
    __half h1 = __float2half_rn(t[g * 4 + 1][cc]);
    __half h2 = __float2half_rn(t[g * 4 + 2][cc]);
    __half h3 = __float2half_rn(t[g * 4 + 3][cc]);
    uint2 uh = make_uint2(
        (uint32_t)__half_as_ushort(h0) | ((uint32_t)__half_as_ushort(h1) << 16),
        (uint32_t)__half_as_ushort(h2) | ((uint32_t)__half_as_ushort(h3) << 16));
    size_t ob = (size_t)(c0 + cc) * R + r0 + g * 4;
    *(uint2*)(o + ob) = uh;
}

// =============================================================================
// GEMM1: h[slot] = relu(x[tok] @ W1t[e]^T + b1[e])
// Single fp16 x fp16 MMA. 4-stage ring, 1 sync/iter, 2 CTAs/SM.
// =============================================================================
__global__ void __launch_bounds__(256, 2) ffn1_kernel(const float* __restrict__ b1) {
    int e = blockIdx.z;
    int cnt = g_count[e];
    int rowTile = blockIdx.y * 128;
    if (rowTile >= cnt) return;
    int sbase = slot_base(e);
    int colTile = blockIdx.x * 128;

    extern __shared__ char sm[];
    uint32_t sb = smem_u32(sm);
    int tid = threadIdx.x;
    int*   toksS = (int*)(sm + SM_TOKS);
    float* biasS = (float*)(sm + SM_BIAS);

    if (tid < 128) {
        int r = rowTile + tid;
        toksS[tid] = (r < cnt) ? g_list[e * N_TOK + r] : 0;
        biasS[tid] = b1[(size_t)e * H_DIM + colTile + tid];
    }
    __syncthreads();

    const int NIT = D_DIM / 32;  // 32

    auto load_stage = [&](int p, int it) {
        int k0 = it * 32;
        uint32_t base = sb + SM_BUF + p * STAGE_B;
#pragma unroll
        for (int j = 0; j < 4; j++) {
            int idx = j * 256 + tid;  // 1024 chunks: A 512 | B 512
            int tile = idx >> 9, v = idx & 511, row = v >> 2, ch = v & 3;
            uint32_t dst = base + tile * TILE_B + row * 64 + (((ch ^ (row >> 1)) & 3) << 4);
            const __half* src;
            if (tile == 0) src = g_x + (size_t)toksS[row] * D_DIM + k0 + ch * 8;
            else           src = g_w1 + (size_t)(e * H_DIM + colTile + row) * D_DIM + k0 + ch * 8;
            CPASYNC16(dst, src);
        }
    };

    int lane = tid & 31, w = tid >> 5;
    int wm = w & 3, wn = w >> 2;
    int aRow0 = wm * 32 + (lane & 15), aRow1 = aRow0 + 16;
    uint32_t aB0 = aRow0 * 64, aB1 = aRow1 * 64;
    int aS0 = (aRow0 >> 1) & 3, aS1 = (aRow1 >> 1) & 3;
    int cA0 = lane >> 4;
    uint32_t bB[4]; int bS[4];
#pragma unroll
    for (int np = 0; np < 4; np++) {
        int n = wn * 64 + np * 16 + (lane & 7) + ((lane & 16) ? 8 : 0);
        bB[np] = n * 64; bS[np] = (n >> 1) & 3;
    }
    int cB0 = (lane >> 3) & 1;

    float c[64];
#pragma unroll
    for (int i = 0; i < 64; i++) c[i] = 0.f;

    load_stage(0, 0); CP_COMMIT();
    load_stage(1, 1); CP_COMMIT();
    load_stage(2, 2); CP_COMMIT();

    int p = 0, pw = 3;
    for (int it = 0; it < NIT; it++) {
        CP_WAIT2();
        __syncthreads();
        uint32_t base = sb + SM_BUF + p * STAGE_B;
#pragma unroll
        for (int ks = 0; ks < 2; ks++) {
            int cA = cA0 + 2 * ks, cB = cB0 + 2 * ks;
            uint32_t ah[8], bh[16];
            LDSM4(ah + 0, base + aB0 + (((cA ^ aS0) & 3) << 4));
            LDSM4(ah + 4, base + aB1 + (((cA ^ aS1) & 3) << 4));
#pragma unroll
            for (int np = 0; np < 4; np++) {
                uint32_t bb = base + bB[np] + (((cB ^ bS[np]) & 3) << 4);
                LDSM4(bh + np * 4, bb + OFF_B);
            }
#pragma unroll
            for (int mi = 0; mi < 2; mi++)
#pragma unroll
                for (int nb = 0; nb < 8; nb++) {
                    float* cc = c + (mi * 8 + nb) * 4;
                    int bi = (nb >> 1) * 4 + (nb & 1) * 2;
                    MMAH(cc, (mi ? ah + 4 : ah), bh[bi], bh[bi + 1]);
                }
        }
        if (it + 3 < NIT) load_stage(pw, it + 3);
        CP_COMMIT();
        p = (p == NSTAGE - 1) ? 0 : p + 1;
        pw = (pw == NSTAGE - 1) ? 0 : pw + 1;
    }

    int g = lane >> 2, tq = lane & 3;
#pragma unroll
    for (int mi = 0; mi < 2; mi++)
#pragma unroll
        for (int half = 0; half < 2; half++) {
            int rloc = wm * 32 + mi * 16 + half * 8 + g;
            if (rowTile + rloc >= cnt) continue;
            size_t hb = ((size_t)(sbase + rowTile + rloc)) * H_DIM + colTile;
#pragma unroll
            for (int nb = 0; nb < 8; nb++) {
                int col = wn * 64 + nb * 8 + tq * 2;
                float v0 = fmaxf(c[(mi * 8 + nb) * 4 + half * 2 + 0] + biasS[col], 0.f);
                float v1 = fmaxf(c[(mi * 8 + nb) * 4 + half * 2 + 1] + biasS[col + 1], 0.f);
                *(uint32_t*)(g_h + hb + col) =
                    (uint32_t)__half_as_ushort(__float2half_rn(v0)) |
                    ((uint32_t)__half_as_ushort(__float2half_rn(v1)) << 16);
            }
        }
}

// =============================================================================
// GEMM2: out[tok] += w * relu(h[slot] @ W2t[e]^T + b2[e])   (same pipeline)
// =============================================================================
__global__ void __launch_bounds__(256, 2) ffn2_kernel(const float* __restrict__ b2,
                                                      float* __restrict__ out) {
    int e = blockIdx.z;
    int cnt = g_count[e];
    int rowTile = blockIdx.y * 128;
    if (rowTile >= cnt) return;
    int sbase = slot_base(e);
    int colTile = blockIdx.x * 128;

    extern __shared__ char sm[];
    uint32_t sb = smem_u32(sm);
    int tid = threadIdx.x;
    int*   toksS = (int*)(sm + SM_TOKS);
    float* wlsS  = (float*)(sm + SM_WLS);
    float* biasS = (float*)(sm + SM_BIAS);

    if (tid < 128) {
        int r = rowTile + tid;
        bool v = (r < cnt);
        toksS[tid] = v ? g_list[e * N_TOK + r] : 0;
        wlsS[tid]  = v ? g_lw[e * N_TOK + r] : 0.f;
        biasS[tid] = b2[(size_t)e * O_DIM + colTile + tid];
    }
    __syncthreads();

    const int NIT = H_DIM / 32;  // 128

    auto load_stage = [&](int p, int it) {
        int k0 = it * 32;
        uint32_t base = sb + SM_BUF + p * STAGE_B;
#pragma unroll
        for (int j = 0; j < 4; j++) {
            int idx = j * 256 + tid;
            int tile = idx >> 9, v = idx & 511, row = v >> 2, ch = v & 3;
            uint32_t dst = base + tile * TILE_B + row * 64 + (((ch ^ (row >> 1)) & 3) << 4);
            const __half* src;
            int arow = sbase + rowTile + row;
            if (arow >= sbase + cnt) arow = sbase;   // clamp (weight 0 in epilogue)
            if (tile == 0) src = g_h + (size_t)arow * H_DIM + k0 + ch * 8;
            else           src = g_w2 + (size_t)(e * O_DIM + colTile + row) * H_DIM + k0 + ch * 8;
            CPASYNC16(dst, src);
        }
    };

    int lane = tid & 31, w = tid >> 5;
    int wm = w & 3, wn = w >> 2;
    int aRow0 = wm * 32 + (lane & 15), aRow1 = aRow0 + 16;
    uint32_t aB0 = aRow0 * 64, aB1 = aRow1 * 64;
    int aS0 = (aRow0 >> 1) & 3, aS1 = (aRow1 >> 1) & 3;
    int cA0 = lane >> 4;
    uint32_t bB[4]; int bS[4];
#pragma unroll
    for (int np = 0; np < 4; np++) {
        int n = wn * 64 + np * 16 + (lane & 7) + ((lane & 16) ? 8 : 0);
        bB[np] = n * 64; bS[np] = (n >> 1) & 3;
    }
    int cB0 = (lane >> 3) & 1;

    float c[64];
#pragma unroll
    for (int i = 0; i < 64; i++) c[i] = 0.f;

    load_stage(0, 0); CP_COMMIT();
    load_stage(1, 1); CP_COMMIT();
    load_stage(2, 2); CP_COMMIT();

    int p = 0, pw = 3;
    for (int it = 0; it < NIT; it++) {
        CP_WAIT2();
        __syncthreads();
        uint32_t base = sb + SM_BUF + p * STAGE_B;
#pragma unroll
        for (int ks = 0; ks < 2; ks++) {
            int cA = cA0 + 2 * ks, cB = cB0 + 2 * ks;
            uint32_t ah[8], bh[16];
            LDSM4(ah + 0, base + aB0 + (((cA ^ aS0) & 3) << 4));
            LDSM4(ah + 4, base + aB1 + (((cA ^ aS1) & 3) << 4));
#pragma unroll
            for (int np = 0; np < 4; np++) {
                uint32_t bb = base + bB[np] + (((cB ^ bS[np]) & 3) << 4);
                LDSM4(bh + np * 4, bb + OFF_B);
            }
#pragma unroll
            for (int mi = 0; mi < 2; mi++)
#pragma unroll
                for (int nb = 0; nb < 8; nb++) {
                    float* cc = c + (mi * 8 + nb) * 4;
                    int bi = (nb >> 1) * 4 + (nb & 1) * 2;
                    MMAH(cc, (mi ? ah + 4 : ah), bh[bi], bh[bi + 1]);
                }
        }
        if (it + 3 < NIT) load_stage(pw, it + 3);
        CP_COMMIT();
        p = (p == NSTAGE - 1) ? 0 : p + 1;
        pw = (pw == NSTAGE - 1) ? 0 : pw + 1;
    }

    int g = lane >> 2, tq = lane & 3;
#pragma unroll
    for (int mi = 0; mi < 2; mi++)
#pragma unroll
        for (int half = 0; half < 2; half++) {
            int rloc = wm * 32 + mi * 16 + half * 8 + g;
            if (rowTile + rloc >= cnt) continue;
            int tok = toksS[rloc];
            float wc = wlsS[rloc];
            float* orow = out + (size_t)tok * O_DIM + colTile;
#pragma unroll
            for (int nb = 0; nb < 8; nb++) {
                int col = wn * 64 + nb * 8 + tq * 2;
                float v0 = fmaxf(c[(mi * 8 + nb) * 4 + half * 2 + 0] + biasS[col], 0.f) * wc;
                float v1 = fmaxf(c[(mi * 8 + nb) * 4 + half * 2 + 1] + biasS[col + 1], 0.f) * wc;
                atomicAdd(orow + col, v0);
                atomicAdd(orow + col + 1, v1);
            }
        }
}

// ---------------- host ----------------
extern "C" void kernel_launch(void* const* d_in, const int* in_sizes, int n_in,
                              void* d_out, int out_size) {
    const float* x  = (const float*)d_in[0];
    const float* Wg = (const float*)d_in[1];
    const float* W1 = (const float*)d_in[2];
    const float* b1 = (const float*)d_in[3];
    const float* W2 = (const float*)d_in[4];
    const float* b2 = (const float*)d_in[5];
    float* out = (float*)d_out;

    cudaFuncSetAttribute(ffn1_kernel, cudaFuncAttributeMaxDynamicSharedMemorySize, SMEM_BYTES);
    cudaFuncSetAttribute(ffn2_kernel, cudaFuncAttributeMaxDynamicSharedMemorySize, SMEM_BYTES);

    // ncu captures the 4th kernel launch -> ffn1.
    transpose_cvt_kernel<<<dim3(H_DIM / 32, D_DIM / 32, E_NUM), 256>>>(W1, 0, D_DIM, H_DIM);
    gate_kernel<<<N_TOK, 256>>>(x, Wg);
    build_lists_kernel<<<E_NUM, 1024>>>();
    ffn1_kernel<<<dim3(H_DIM / 128, N_TOK / 128, E_NUM), 256, SMEM_BYTES>>>(b1);
    transpose_cvt_kernel<<<dim3(O_DIM / 32, H_DIM / 32, E_NUM), 256>>>(W2, 1, H_DIM, O_DIM);
    cudaMemsetAsync(out, 0, (size_t)N_TOK * O_DIM * sizeof(float), 0);
    ffn2_kernel<<<dim3(O_DIM / 128, N_TOK / 128, E_NUM), 256, SMEM_BYTES>>>(b2, out);
}

// round 16
// speedup vs baseline: 3.2643x; 1.0523x over previous
#include <cuda_runtime.h>
#include <cuda_fp16.h>
#include <stdint.h>
#include <math.h>

#define N_TOK 4096
#define D_DIM 1024
#define H_DIM 4096
#define O_DIM 1024
#define E_NUM 8

// ---------------- static device scratch ----------------
__device__ __half g_x[(size_t)N_TOK * D_DIM];            // x fp16
__device__ __half g_w1[(size_t)E_NUM * H_DIM * D_DIM];   // [e][h][d] (transposed fp16)
__device__ __half g_w2[(size_t)E_NUM * O_DIM * H_DIM];   // [e][o][h] (transposed fp16)
__device__ __half g_h[(size_t)2 * N_TOK * H_DIM];        // compact slots fp16
__device__ int   g_sel[N_TOK * 2];
__device__ float g_w[N_TOK * 2];
__device__ int   g_list[E_NUM * N_TOK];
__device__ float g_lw[E_NUM * N_TOK];
__device__ int   g_count[E_NUM];

// ---------------- PTX helpers (sm_80-baseline only) ----------------
__device__ __forceinline__ uint32_t smem_u32(const void* p) {
    uint32_t a;
    asm("{ .reg .u64 t; cvta.to.shared.u64 t, %1; cvt.u32.u64 %0, t; }" : "=r"(a) : "l"(p));
    return a;
}

#define CPASYNC16(dst, src) \
    asm volatile("cp.async.cg.shared.global [%0], [%1], 16;" :: "r"(dst), "l"(src))
#define CP_COMMIT() asm volatile("cp.async.commit_group;" ::: "memory")
#define CP_WAIT1()  asm volatile("cp.async.wait_group 1;" ::: "memory")

#define LDSM4(r, a) \
    asm volatile("ldmatrix.sync.aligned.m8n8.x4.shared.b16 {%0,%1,%2,%3}, [%4];" \
                 : "=r"((r)[0]), "=r"((r)[1]), "=r"((r)[2]), "=r"((r)[3]) : "r"(a))

#define MMAH(c, a, b0, b1) \
    asm volatile("mma.sync.aligned.m16n8k16.row.col.f32.f16.f16.f32 " \
                 "{%0,%1,%2,%3}, {%4,%5,%6,%7}, {%8,%9}, {%0,%1,%2,%3};" \
                 : "+f"((c)[0]), "+f"((c)[1]), "+f"((c)[2]), "+f"((c)[3]) \
                 : "r"((a)[0]), "r"((a)[1]), "r"((a)[2]), "r"((a)[3]), "r"(b0), "r"(b1))

// ---------------- smem layout ----------------
// BK=64 stages. Tile: 128 rows x 128 B (64 fp16), 8 chunks of 16 B per row,
// chunk c stored at ((c ^ (row & 7)) * 16) — conflict-free for cp.async writes
// and for every ldmatrix 8-row phase.
// stage = A(16384) | B(16384) = 32768 B; 3 stages + 2048 hdr = 100352 B
// -> 2 CTAs/SM (200704 <= 228KB carveout), prefetch distance 2 stages.
#define SM_TOKS 0
#define SM_WLS  512
#define SM_BIAS 1024
#define SM_BUF  2048
#define TILE_B   16384
#define STAGE_B  32768
#define OFF_B    TILE_B
#define NSTAGE   3
#define SMEM_BYTES (SM_BUF + NSTAGE * STAGE_B)

// ---------------- gate + x convert (fused) ----------------
__global__ void gate_kernel(const float* __restrict__ x, const float* __restrict__ Wg) {
    int t = blockIdx.x;
    int tid = threadIdx.x;  // 256 threads, 4 cols each
    float4 v = ((const float4*)(x + (size_t)t * D_DIM))[tid];
    float vv[4] = {v.x, v.y, v.z, v.w};

    uint32_t ph[2];
#pragma unroll
    for (int j = 0; j < 4; j++) {
        uint32_t hbits = (uint32_t)__half_as_ushort(__float2half_rn(vv[j]));
        if (j & 1) ph[j >> 1] |= hbits << 16;
        else       ph[j >> 1]  = hbits;
    }
    size_t xo = ((size_t)t * D_DIM + tid * 4) >> 2;
    ((uint2*)g_x)[xo] = make_uint2(ph[0], ph[1]);

    float acc[E_NUM];
#pragma unroll
    for (int e = 0; e < E_NUM; e++) acc[e] = 0.f;
#pragma unroll
    for (int j = 0; j < 4; j++) {
        int d = tid * 4 + j;
        const float4 w0 = *(const float4*)(Wg + (size_t)d * E_NUM);
        const float4 w1 = *(const float4*)(Wg + (size_t)d * E_NUM + 4);
        acc[0] += vv[j] * w0.x; acc[1] += vv[j] * w0.y;
        acc[2] += vv[j] * w0.z; acc[3] += vv[j] * w0.w;
        acc[4] += vv[j] * w1.x; acc[5] += vv[j] * w1.y;
        acc[6] += vv[j] * w1.z; acc[7] += vv[j] * w1.w;
    }

    __shared__ float red[E_NUM][256];
#pragma unroll
    for (int e = 0; e < E_NUM; e++) red[e][tid] = acc[e];
    __syncthreads();
    for (int s = 128; s > 0; s >>= 1) {
        if (tid < s) {
#pragma unroll
            for (int e = 0; e < E_NUM; e++) red[e][tid] += red[e][tid + s];
        }
        __syncthreads();
    }
    if (tid == 0) {
        float v2[E_NUM];
#pragma unroll
        for (int e = 0; e < E_NUM; e++) v2[e] = fmaxf(red[e][0], 0.f);
        int i1 = 0; float m1 = v2[0];
#pragma unroll
        for (int e = 1; e < E_NUM; e++) if (v2[e] > m1) { m1 = v2[e]; i1 = e; }
        int i2 = -1; float m2 = -1e30f;
#pragma unroll
        for (int e = 0; e < E_NUM; e++) if (e != i1 && v2[e] > m2) { m2 = v2[e]; i2 = e; }
        float eb = __expf(m2 - m1);
        float inv = 1.f / (1.f + eb);
        g_sel[t * 2 + 0] = i1;  g_w[t * 2 + 0] = inv;
        g_sel[t * 2 + 1] = i2;  g_w[t * 2 + 1] = eb * inv;
    }
}

// ---------------- per-expert token lists (deterministic scan) ----------------
__global__ void build_lists_kernel() {
    int e = blockIdx.x;
    int tid = threadIdx.x;  // 1024
    __shared__ int ssum[1024];
    int t0 = tid * 4;
    int flag[4]; float wv[4];
    int cnt = 0;
#pragma unroll
    for (int j = 0; j < 4; j++) {
        int t = t0 + j;
        int s0 = g_sel[t * 2], s1 = g_sel[t * 2 + 1];
        flag[j] = 0; wv[j] = 0.f;
        if (s0 == e)      { flag[j] = 1; wv[j] = g_w[t * 2]; }
        else if (s1 == e) { flag[j] = 1; wv[j] = g_w[t * 2 + 1]; }
        cnt += flag[j];
    }
    ssum[tid] = cnt;
    __syncthreads();
    for (int off = 1; off < 1024; off <<= 1) {
        int v = (tid >= off) ? ssum[tid - off] : 0;
        __syncthreads();
        ssum[tid] += v;
        __syncthreads();
    }
    int pos = ssum[tid] - cnt;
#pragma unroll
    for (int j = 0; j < 4; j++) {
        if (flag[j]) {
            g_list[e * N_TOK + pos] = t0 + j;
            g_lw[e * N_TOK + pos] = wv[j];
            pos++;
        }
    }
    if (tid == 1023) g_count[e] = ssum[1023];
}

__device__ __forceinline__ int slot_base(int e) {
    int b = 0;
#pragma unroll
    for (int i = 0; i < E_NUM; i++) if (i < e) b += g_count[i];
    return b;
}

// in: [e][R][C] fp32 -> out: [e][C][R] fp16, selected INSIDE device code
__global__ void transpose_cvt_kernel(const float* __restrict__ in, int which, int R, int C) {
    int e = blockIdx.z;
    const float* src = in + (size_t)e * R * C;
    __half* o = (which ? g_w2 : g_w1) + (size_t)e * R * C;
    __shared__ float t[32][33];
    int tid = threadIdx.x;
    int tx = tid & 31, ty = tid >> 5;
    int c0 = blockIdx.x * 32, r0 = blockIdx.y * 32;
#pragma unroll
    for (int j = 0; j < 4; j++)
        t[ty + 8 * j][tx] = src[(size_t)(r0 + ty + 8 * j) * C + c0 + tx];
    __syncthreads();
    int cc = tid >> 3, g = tid & 7;
    __half h0 = __float2half_rn(t[g * 4 + 0][cc]);
    __half h1 = __float2half_rn(t[g * 4 + 1][cc]);
    __half h2 = __float2half_rn(t[g * 4 + 2][cc]);
    __half h3 = __float2half_rn(t[g * 4 + 3][cc]);
    uint2 uh = make_uint2(
        (uint32_t)__half_as_ushort(h0) | ((uint32_t)__half_as_ushort(h1) << 16),
        (uint32_t)__half_as_ushort(h2) | ((uint32_t)__half_as_ushort(h3) << 16));
    size_t ob = (size_t)(c0 + cc) * R + r0 + g * 4;
    *(uint2*)(o + ob) = uh;
}

// =============================================================================
// GEMM1: h[slot] = relu(x[tok] @ W1t[e]^T + b1[e])
// fp16 x fp16 MMA, BK=64 stages, 3-stage ring, 1 sync per 64-K iteration.
// =============================================================================
__global__ void __launch_bounds__(256, 2) ffn1_kernel(const float* __restrict__ b1) {
    int e = blockIdx.z;
    int cnt = g_count[e];
    int rowTile = blockIdx.y * 128;
    if (rowTile >= cnt) return;
    int sbase = slot_base(e);
    int colTile = blockIdx.x * 128;

    extern __shared__ char sm[];
    uint32_t sb = smem_u32(sm);
    int tid = threadIdx.x;
    int*   toksS = (int*)(sm + SM_TOKS);
    float* biasS = (float*)(sm + SM_BIAS);

    if (tid < 128) {
        int r = rowTile + tid;
        toksS[tid] = (r < cnt) ? g_list[e * N_TOK + r] : 0;
        biasS[tid] = b1[(size_t)e * H_DIM + colTile + tid];
    }
    __syncthreads();

    const int NIT = D_DIM / 64;  // 16

    auto load_stage = [&](int p, int it) {
        int k0 = it * 64;
        uint32_t base = sb + SM_BUF + p * STAGE_B;
#pragma unroll
        for (int j = 0; j < 8; j++) {
            int idx = j * 256 + tid;  // 2048 chunks: A 1024 | B 1024
            int tile = idx >> 10, v = idx & 1023, row = v >> 3, ch = v & 7;
            uint32_t dst = base + tile * TILE_B + row * 128 + (((ch ^ row) & 7) << 4);
            const __half* src;
            if (tile == 0) src = g_x + (size_t)toksS[row] * D_DIM + k0 + ch * 8;
            else           src = g_w1 + (size_t)(e * H_DIM + colTile + row) * D_DIM + k0 + ch * 8;
            CPASYNC16(dst, src);
        }
    };

    int lane = tid & 31, w = tid >> 5;
    int wm = w & 3, wn = w >> 2;
    int aRow0 = wm * 32 + (lane & 15), aRow1 = aRow0 + 16;
    uint32_t aB0 = aRow0 * 128, aB1 = aRow1 * 128;
    int aS0 = aRow0 & 7, aS1 = aRow1 & 7;
    int cA0 = lane >> 4;               // 0/1
    uint32_t bB[4]; int bS[4];
#pragma unroll
    for (int np = 0; np < 4; np++) {
        int n = wn * 64 + np * 16 + (lane & 7) + ((lane & 16) ? 8 : 0);
        bB[np] = n * 128; bS[np] = n & 7;
    }
    int cB0 = (lane >> 3) & 1;         // 0/1

    float c[64];
#pragma unroll
    for (int i = 0; i < 64; i++) c[i] = 0.f;

    load_stage(0, 0); CP_COMMIT();
    load_stage(1, 1); CP_COMMIT();

    int p = 0, pw = 2;
    for (int it = 0; it < NIT; it++) {
        CP_WAIT1();
        __syncthreads();
        uint32_t base = sb + SM_BUF + p * STAGE_B;
#pragma unroll
        for (int ks = 0; ks < 4; ks++) {
            int cA = cA0 + 2 * ks, cB = cB0 + 2 * ks;
            uint32_t ah[8], bh[16];
            LDSM4(ah + 0, base + aB0 + (((cA ^ aS0) & 7) << 4));
            LDSM4(ah + 4, base + aB1 + (((cA ^ aS1) & 7) << 4));
#pragma unroll
            for (int np = 0; np < 4; np++) {
                uint32_t bb = base + OFF_B + bB[np] + (((cB ^ bS[np]) & 7) << 4);
                LDSM4(bh + np * 4, bb);
            }
#pragma unroll
            for (int mi = 0; mi < 2; mi++)
#pragma unroll
                for (int nb = 0; nb < 8; nb++) {
                    float* cc = c + (mi * 8 + nb) * 4;
                    int bi = (nb >> 1) * 4 + (nb & 1) * 2;
                    MMAH(cc, (mi ? ah + 4 : ah), bh[bi], bh[bi + 1]);
                }
        }
        if (it + 2 < NIT) load_stage(pw, it + 2);
        CP_COMMIT();
        p = (p == NSTAGE - 1) ? 0 : p + 1;
        pw = (pw == NSTAGE - 1) ? 0 : pw + 1;
    }

    int g = lane >> 2, tq = lane & 3;
#pragma unroll
    for (int mi = 0; mi < 2; mi++)
#pragma unroll
        for (int half = 0; half < 2; half++) {
            int rloc = wm * 32 + mi * 16 + half * 8 + g;
            if (rowTile + rloc >= cnt) continue;
            size_t hb = ((size_t)(sbase + rowTile + rloc)) * H_DIM + colTile;
#pragma unroll
            for (int nb = 0; nb < 8; nb++) {
                int col = wn * 64 + nb * 8 + tq * 2;
                float v0 = fmaxf(c[(mi * 8 + nb) * 4 + half * 2 + 0] + biasS[col], 0.f);
                float v1 = fmaxf(c[(mi * 8 + nb) * 4 + half * 2 + 1] + biasS[col + 1], 0.f);
                *(uint32_t*)(g_h + hb + col) =
                    (uint32_t)__half_as_ushort(__float2half_rn(v0)) |
                    ((uint32_t)__half_as_ushort(__float2half_rn(v1)) << 16);
            }
        }
}

// =============================================================================
// GEMM2: out[tok] += w * relu(h[slot] @ W2t[e]^T + b2[e])   (same pipeline)
// =============================================================================
__global__ void __launch_bounds__(256, 2) ffn2_kernel(const float* __restrict__ b2,
                                                      float* __restrict__ out) {
    int e = blockIdx.z;
    int cnt = g_count[e];
    int rowTile = blockIdx.y * 128;
    if (rowTile >= cnt) return;
    int sbase = slot_base(e);
    int colTile = blockIdx.x * 128;

    extern __shared__ char sm[];
    uint32_t sb = smem_u32(sm);
    int tid = threadIdx.x;
    int*   toksS = (int*)(sm + SM_TOKS);
    float* wlsS  = (float*)(sm + SM_WLS);
    float* biasS = (float*)(sm + SM_BIAS);

    if (tid < 128) {
        int r = rowTile + tid;
        bool v = (r < cnt);
        toksS[tid] = v ? g_list[e * N_TOK + r] : 0;
        wlsS[tid]  = v ? g_lw[e * N_TOK + r] : 0.f;
        biasS[tid] = b2[(size_t)e * O_DIM + colTile + tid];
    }
    __syncthreads();

    const int NIT = H_DIM / 64;  // 64

    auto load_stage = [&](int p, int it) {
        int k0 = it * 64;
        uint32_t base = sb + SM_BUF + p * STAGE_B;
#pragma unroll
        for (int j = 0; j < 8; j++) {
            int idx = j * 256 + tid;
            int tile = idx >> 10, v = idx & 1023, row = v >> 3, ch = v & 7;
            uint32_t dst = base + tile * TILE_B + row * 128 + (((ch ^ row) & 7) << 4);
            const __half* src;
            int arow = sbase + rowTile + row;
            if (arow >= sbase + cnt) arow = sbase;   // clamp (weight 0 in epilogue)
            if (tile == 0) src = g_h + (size_t)arow * H_DIM + k0 + ch * 8;
            else           src = g_w2 + (size_t)(e * O_DIM + colTile + row) * H_DIM + k0 + ch * 8;
            CPASYNC16(dst, src);
        }
    };

    int lane = tid & 31, w = tid >> 5;
    int wm = w & 3, wn = w >> 2;
    int aRow0 = wm * 32 + (lane & 15), aRow1 = aRow0 + 16;
    uint32_t aB0 = aRow0 * 128, aB1 = aRow1 * 128;
    int aS0 = aRow0 & 7, aS1 = aRow1 & 7;
    int cA0 = lane >> 4;
    uint32_t bB[4]; int bS[4];
#pragma unroll
    for (int np = 0; np < 4; np++) {
        int n = wn * 64 + np * 16 + (lane & 7) + ((lane & 16) ? 8 : 0);
        bB[np] = n * 128; bS[np] = n & 7;
    }
    int cB0 = (lane >> 3) & 1;

    float c[64];
#pragma unroll
    for (int i = 0; i < 64; i++) c[i] = 0.f;

    load_stage(0, 0); CP_COMMIT();
    load_stage(1, 1); CP_COMMIT();

    int p = 0, pw = 2;
    for (int it = 0; it < NIT; it++) {
        CP_WAIT1();
        __syncthreads();
        uint32_t base = sb + SM_BUF + p * STAGE_B;
#pragma unroll
        for (int ks = 0; ks < 4; ks++) {
            int cA = cA0 + 2 * ks, cB = cB0 + 2 * ks;
            uint32_t ah[8], bh[16];
            LDSM4(ah + 0, base + aB0 + (((cA ^ aS0) & 7) << 4));
            LDSM4(ah + 4, base + aB1 + (((cA ^ aS1) & 7) << 4));
#pragma unroll
            for (int np = 0; np < 4; np++) {
                uint32_t bb = base + OFF_B + bB[np] + (((cB ^ bS[np]) & 7) << 4);
                LDSM4(bh + np * 4, bb);
            }
#pragma unroll
            for (int mi = 0; mi < 2; mi++)
#pragma unroll
                for (int nb = 0; nb < 8; nb++) {
                    float* cc = c + (mi * 8 + nb) * 4;
                    int bi = (nb >> 1) * 4 + (nb & 1) * 2;
                    MMAH(cc, (mi ? ah + 4 : ah), bh[bi], bh[bi + 1]);
                }
        }
        if (it + 2 < NIT) load_stage(pw, it + 2);
        CP_COMMIT();
        p = (p == NSTAGE - 1) ? 0 : p + 1;
        pw = (pw == NSTAGE - 1) ? 0 : pw + 1;
    }

    int g = lane >> 2, tq = lane & 3;
#pragma unroll
    for (int mi = 0; mi < 2; mi++)
#pragma unroll
        for (int half = 0; half < 2; half++) {
            int rloc = wm * 32 + mi * 16 + half * 8 + g;
            if (rowTile + rloc >= cnt) continue;
            int tok = toksS[rloc];
            float wc = wlsS[rloc];
            float* orow = out + (size_t)tok * O_DIM + colTile;
#pragma unroll
            for (int nb = 0; nb < 8; nb++) {
                int col = wn * 64 + nb * 8 + tq * 2;
                float v0 = fmaxf(c[(mi * 8 + nb) * 4 + half * 2 + 0] + biasS[col], 0.f) * wc;
                float v1 = fmaxf(c[(mi * 8 + nb) * 4 + half * 2 + 1] + biasS[col + 1], 0.f) * wc;
                atomicAdd(orow + col, v0);
                atomicAdd(orow + col + 1, v1);
            }
        }
}

// ---------------- host ----------------
extern "C" void kernel_launch(void* const* d_in, const int* in_sizes, int n_in,
                              void* d_out, int out_size) {
    const float* x  = (const float*)d_in[0];
    const float* Wg = (const float*)d_in[1];
    const float* W1 = (const float*)d_in[2];
    const float* b1 = (const float*)d_in[3];
    const float* W2 = (const float*)d_in[4];
    const float* b2 = (const float*)d_in[5];
    float* out = (float*)d_out;

    cudaFuncSetAttribute(ffn1_kernel, cudaFuncAttributeMaxDynamicSharedMemorySize, SMEM_BYTES);
    cudaFuncSetAttribute(ffn2_kernel, cudaFuncAttributeMaxDynamicSharedMemorySize, SMEM_BYTES);

    // ncu captures the 4th kernel launch -> ffn1.
    transpose_cvt_kernel<<<dim3(H_DIM / 32, D_DIM / 32, E_NUM), 256>>>(W1, 0, D_DIM, H_DIM);
    gate_kernel<<<N_TOK, 256>>>(x, Wg);
    build_lists_kernel<<<E_NUM, 1024>>>();
    ffn1_kernel<<<dim3(H_DIM / 128, N_TOK / 128, E_NUM), 256, SMEM_BYTES>>>(b1);
    transpose_cvt_kernel<<<dim3(O_DIM / 32, H_DIM / 32, E_NUM), 256>>>(W2, 1, H_DIM, O_DIM);
    cudaMemsetAsync(out, 0, (size_t)N_TOK * O_DIM * sizeof(float), 0);
    ffn2_kernel<<<dim3(O_DIM / 128, N_TOK / 128, E_NUM), 256, SMEM_BYTES>>>(b2, out);
}